// round 15
// baseline (speedup 1.0000x reference)
#include <cuda_runtime.h>
#include <cuda_fp16.h>
#include <stdint.h>

#define NN 10000
#define NE 160000
#define MTILES 79  // ceil(10000/128)

#if defined(__CUDA_ARCH_FEAT_SM103_ALL) || defined(__CUDA_ARCH_FEAT_SM100_ALL)
#define HAS_TC 1
#else
#define HAS_TC 0
#endif

// ------------------------- device scratch -------------------------
__device__ int g_deg[NN];
__device__ int g_cur[NN];
__device__ int g_srcs[NE];
__device__ int g_dsts[NE];

__device__ float  g_A1f[NN * 64];
__device__ float  g_B1f[NN * 64];
__device__ float  g_agg1[NN * 128];
__device__ __half g_agg1hl[NN * 256];
__device__ __half g_T1hl[NN * 512];
__device__ float  g_P1[NN * 512];
__device__ __half g_H1hl[NN * 1024];
__device__ float  g_C2f[NN * 1024];
__device__ float  g_D2f[NN * 1024];
__device__ float  g_agg2[NN * 1024];
__device__ __half g_agg2hl[NN * 2048];
__device__ __half g_U2hl[NN * 4096];
__device__ float  g_P2[NN * 2048];
__device__ float  g_mu[2048];
__device__ float  g_rs[2048];
__device__ float  g_part[MTILES * 2048];
__device__ float  g_partq[MTILES * 2048];

// edge activations (CSR order): [p][0,1024)=hi, [1024,2048)=lo
__device__ __half g_ACT[(size_t)NE * 2048];

// split weights, layout [F, 2K]: [0,K)=hi, [K,2K)=lo (legacy mma kernels)
__device__ __half g_W_l1w2[128 * 128];
__device__ __half g_W_g1w1[256 * 256];
__device__ __half g_W_g1w2[512 * 512];
__device__ __half g_W_l2w1[1024 * 1024];
__device__ __half g_W_l2w2[1024 * 2048];
__device__ __half g_W_g2w1[2048 * 2048];
__device__ __half g_W_g2w2[2048 * 4096];

// l2w2 pre-swizzled for tcgen05: [y(4)][chunk(32)][hi 8192 | lo 8192] halves,
// each tile = 256 rows x 32 halves (64B rows), SW64-swizzled.
__device__ __half g_W2sw[4 * 32 * 2 * 8192];

// ------------------------- helpers -------------------------
__device__ __forceinline__ float leaky1f(float v) { return v > 0.0f ? v : 0.05f * v; }

__device__ __forceinline__ void atomicMaxF(float* addr, float v) {
    if (v >= 0.0f) atomicMax((int*)addr, __float_as_int(v));
    else           atomicMin((unsigned int*)addr, (unsigned int)__float_as_int(v));
}

__device__ __forceinline__ uint32_t smem_u32(const void* p) {
    return (uint32_t)__cvta_generic_to_shared(p);
}

__device__ __forceinline__ void cp16(uint32_t dst, const void* src) {
    asm volatile("cp.async.cg.shared.global [%0], [%1], 16;" :: "r"(dst), "l"(src));
}
__device__ __forceinline__ void cp_commit() {
    asm volatile("cp.async.commit_group;" ::: "memory");
}
__device__ __forceinline__ void cp_wait0() {
    asm volatile("cp.async.wait_group 0;" ::: "memory");
}
__device__ __forceinline__ void cp_wait1() {
    asm volatile("cp.async.wait_group 1;" ::: "memory");
}
__device__ __forceinline__ void cp_wait2() {
    asm volatile("cp.async.wait_group 2;" ::: "memory");
}

// ---- legacy mma.sync path ----
__device__ __forceinline__ void ldsm_x4(uint32_t& r0, uint32_t& r1, uint32_t& r2, uint32_t& r3,
                                        uint32_t addr) {
    asm volatile("ldmatrix.sync.aligned.m8n8.x4.shared.b16 {%0,%1,%2,%3}, [%4];"
                 : "=r"(r0), "=r"(r1), "=r"(r2), "=r"(r3) : "r"(addr));
}

__device__ __forceinline__ void mma16816(float c[4], const uint32_t a[4], const uint32_t b[2]) {
    asm volatile(
        "mma.sync.aligned.m16n8k16.row.col.f32.f16.f16.f32 "
        "{%0,%1,%2,%3},{%4,%5,%6,%7},{%8,%9},{%0,%1,%2,%3};"
        : "+f"(c[0]), "+f"(c[1]), "+f"(c[2]), "+f"(c[3])
        : "r"(a[0]), "r"(a[1]), "r"(a[2]), "r"(a[3]), "r"(b[0]), "r"(b[1]));
}

// standard chunk: one A x one B over K=32
__device__ __forceinline__ void mma_chunk(const __half* As, const __half* Bs, int lane,
                                          int wm, int wn, float c[4][4][4]) {
#pragma unroll
    for (int ks = 0; ks < 2; ks++) {
        const int k0 = ks * 16;
        uint32_t a[4][4];
#pragma unroll
        for (int mf = 0; mf < 4; mf++) {
            const __half* ap = As + (wm * 64 + mf * 16 + (lane & 15)) * 40 + k0 + ((lane >> 4) << 3);
            ldsm_x4(a[mf][0], a[mf][1], a[mf][2], a[mf][3], smem_u32(ap));
        }
        uint32_t b[4][2];
#pragma unroll
        for (int p = 0; p < 2; p++) {
            const __half* bp = Bs + (wn * 32 + p * 16 + (lane & 7) + ((lane >> 4) << 3)) * 40
                               + k0 + (((lane >> 3) & 1) << 3);
            uint32_t r0, r1, r2, r3;
            ldsm_x4(r0, r1, r2, r3, smem_u32(bp));
            b[2 * p][0] = r0; b[2 * p][1] = r1; b[2 * p + 1][0] = r2; b[2 * p + 1][1] = r3;
        }
#pragma unroll
        for (int mf = 0; mf < 4; mf++)
#pragma unroll
            for (int nf = 0; nf < 4; nf++)
                mma16816(c[mf][nf], a[mf], b[nf]);
    }
}

// fused chunk: A-fragments loaded ONCE, used against Bh and Bl
__device__ __forceinline__ void mma_chunk_abb(const __half* As, const __half* Bh_,
                                              const __half* Bl_, int lane, int wm, int wn,
                                              float c[4][4][4]) {
#pragma unroll
    for (int ks = 0; ks < 2; ks++) {
        const int k0 = ks * 16;
        uint32_t a[4][4];
#pragma unroll
        for (int mf = 0; mf < 4; mf++) {
            const __half* ap = As + (wm * 64 + mf * 16 + (lane & 15)) * 40 + k0 + ((lane >> 4) << 3);
            ldsm_x4(a[mf][0], a[mf][1], a[mf][2], a[mf][3], smem_u32(ap));
        }
        uint32_t bh[4][2], bl[4][2];
#pragma unroll
        for (int p = 0; p < 2; p++) {
            int boff = (wn * 32 + p * 16 + (lane & 7) + ((lane >> 4) << 3)) * 40
                       + k0 + (((lane >> 3) & 1) << 3);
            uint32_t r0, r1, r2, r3;
            ldsm_x4(r0, r1, r2, r3, smem_u32(Bh_ + boff));
            bh[2 * p][0] = r0; bh[2 * p][1] = r1; bh[2 * p + 1][0] = r2; bh[2 * p + 1][1] = r3;
            ldsm_x4(r0, r1, r2, r3, smem_u32(Bl_ + boff));
            bl[2 * p][0] = r0; bl[2 * p][1] = r1; bl[2 * p + 1][0] = r2; bl[2 * p + 1][1] = r3;
        }
#pragma unroll
        for (int mf = 0; mf < 4; mf++)
#pragma unroll
            for (int nf = 0; nf < 4; nf++)
                mma16816(c[mf][nf], a[mf], bh[nf]);
#pragma unroll
        for (int mf = 0; mf < 4; mf++)
#pragma unroll
            for (int nf = 0; nf < 4; nf++)
                mma16816(c[mf][nf], a[mf], bl[nf]);
    }
}

#if HAS_TC
// ---- tcgen05 helpers (arch-specific pass only) ----
__device__ __forceinline__ uint32_t elect_one_pred() {
    uint32_t pred;
    asm volatile(
        "{\n\t.reg .pred p;\n\telect.sync _|p, 0xFFFFFFFF;\n\t"
        "selp.b32 %0, 1, 0, p;\n\t}" : "=r"(pred));
    return pred;
}

// SW64 K-major descriptor: layout=4, version=1 (Blackwell), SBO=32 (512B = 8 rows x 64B), LBO=1
static constexpr uint64_t SMEM_DESC_BASE_SW64 =
    (uint64_t(4) << 61) | (uint64_t(1) << 46) | (uint64_t(32) << 32) | (uint64_t(1) << 16);

__device__ __forceinline__ uint64_t make_desc64(uint32_t addr) {
    return SMEM_DESC_BASE_SW64 | ((uint64_t)(addr >> 4) & 0x3FFF);
}

__device__ __forceinline__ void mma_f16_ss_cg1(uint32_t d_tmem, uint64_t a_desc, uint64_t b_desc,
                                               uint32_t idesc, uint32_t en) {
    asm volatile(
        "{\n\t.reg .pred p;\n\tsetp.ne.u32 p, %5, 0;\n\t"
        "tcgen05.mma.cta_group::1.kind::f16 [%0], %1, %2, %3, {%4,%4,%4,%4}, p;\n\t}"
        :: "r"(d_tmem), "l"(a_desc), "l"(b_desc), "r"(idesc), "r"(0u), "r"(en)
        : "memory");
}

__device__ __forceinline__ void mbar_init(uint32_t addr, uint32_t cnt) {
    asm volatile("mbarrier.init.shared.b64 [%0], %1;" :: "r"(addr), "r"(cnt) : "memory");
}

__device__ __forceinline__ void mbar_wait(uint32_t addr, uint32_t parity) {
    asm volatile(
        "{\n\t.reg .pred P1;\n\t"
        "WAIT_%=:\n\t"
        "mbarrier.try_wait.parity.acquire.cta.shared::cta.b64 P1, [%0], %1, 0x989680;\n\t"
        "@P1 bra.uni DONE_%=;\n\t"
        "bra.uni WAIT_%=;\n\t"
        "DONE_%=:\n\t}"
        :: "r"(addr), "r"(parity) : "memory");
}
#endif  // HAS_TC

// ------------------------- small kernels -------------------------
__global__ void k_init() {
    int idx = blockIdx.x * blockDim.x + threadIdx.x;
    const float NEGINF = __int_as_float(0xff800000);
    if (idx < NN) g_deg[idx] = 0;
    if (idx < NN * 128) g_agg1[idx] = NEGINF;
    if (idx < NN * 1024) g_agg2[idx] = NEGINF;
}

__global__ void k_hist(const int* __restrict__ ei) {
    int e = blockIdx.x * blockDim.x + threadIdx.x;
    if (e < NE) atomicAdd(&g_deg[ei[NE + e]], 1);
}

__global__ void k_scan() {
    __shared__ int part[1024];
    int t = threadIdx.x;
    int base = t * 10;
    int loc[10];
    int s = 0;
#pragma unroll
    for (int i = 0; i < 10; i++) {
        int idx = base + i;
        int v = (idx < NN) ? g_deg[idx] : 0;
        loc[i] = s; s += v;
    }
    part[t] = s;
    __syncthreads();
    for (int off = 1; off < 1024; off <<= 1) {
        int v = 0;
        if (t >= off) v = part[t - off];
        __syncthreads();
        if (t >= off) part[t] += v;
        __syncthreads();
    }
    int excl = (t == 0) ? 0 : part[t - 1];
#pragma unroll
    for (int i = 0; i < 10; i++) {
        int idx = base + i;
        if (idx < NN) g_cur[idx] = excl + loc[i];
    }
}

__global__ void k_scatter(const int* __restrict__ ei) {
    int e = blockIdx.x * blockDim.x + threadIdx.x;
    if (e < NE) {
        int d = ei[NE + e];
        int p = atomicAdd(&g_cur[d], 1);
        g_srcs[p] = ei[e];
        g_dsts[p] = d;
    }
}

// W[K,F] fp32 -> split Wt[F,2K] (hi | lo), smem-tiled for coalesced writes
__global__ void k_cvtT_split_t(const float* __restrict__ W, __half* __restrict__ Wt,
                               int K, int F) {
    __shared__ float tile[32][33];
    int kt = blockIdx.y * 32, ft = blockIdx.x * 32;
    int tx = threadIdx.x, ty = threadIdx.y;  // 32 x 8
#pragma unroll
    for (int i = 0; i < 32; i += 8)
        tile[ty + i][tx] = W[(size_t)(kt + ty + i) * F + ft + tx];
    __syncthreads();
#pragma unroll
    for (int i = 0; i < 32; i += 8) {
        int f = ft + ty + i, k = kt + tx;
        float v = tile[tx][ty + i];
        __half hi = __float2half(v);
        Wt[(size_t)f * 2 * K + k] = hi;
        Wt[(size_t)f * 2 * K + K + k] = __float2half(v - __half2float(hi));
    }
}

// l2w2 [1024 K][1024 F] fp32 -> SW64-swizzled tcgen05 tiles (K=32 chunks, 256-row tiles)
__global__ void k_cvt_w2sw(const float* __restrict__ W) {
    int idx = blockIdx.x * blockDim.x + threadIdx.x;
    if (idx >= 1024 * 1024) return;
    int f = idx >> 10, k = idx & 1023;
    float v = W[k * 1024 + f];
    __half hi = __float2half(v);
    __half lo = __float2half(v - __half2float(hi));
    int y = f >> 8, r = f & 255, ch = k >> 5, c = k & 31;
    uint32_t bo = (uint32_t)(r * 64 + c * 2);
    uint32_t sw = bo ^ ((bo >> 3) & 0x30);
    size_t base = (size_t)(y * 32 + ch) * 16384;
    g_W2sw[base + (sw >> 1)] = hi;
    g_W2sw[base + 8192 + (sw >> 1)] = lo;
}

// conv1 node precompute (fp32): A1 = x·(Wx+Wp)+b ; B1 = x·Wp
__global__ void k_precomp1(const float* __restrict__ x, const float* __restrict__ w,
                           const float* __restrict__ b) {
    int idx = blockIdx.x * blockDim.x + threadIdx.x;
    if (idx >= NN * 64) return;
    int n = idx >> 6, f = idx & 63;
    float x0 = x[2 * n], x1 = x[2 * n + 1];
    float w0 = w[f], w1 = w[64 + f], w2 = w[128 + f], w3 = w[192 + f];
    g_A1f[idx] = x0 * (w0 + w2) + x1 * (w1 + w3) + b[f];
    g_B1f[idx] = x0 * w2 + x1 * w3;
}

// conv2 pos precompute: D2 = x·Wp (rows 512,513 of l2w1 [514,1024])
__global__ void k_precompD2(const float* __restrict__ x, const float* __restrict__ l2w1) {
    int idx = blockIdx.x * blockDim.x + threadIdx.x;
    if (idx >= NN * 1024) return;
    int n = idx >> 10, f = idx & 1023;
    g_D2f[idx] = x[2 * n] * l2w1[512 * 1024 + f] + x[2 * n + 1] * l2w1[513 * 1024 + f];
}

// edge activations: ACT[p] = split(leaky(C2[src[p]] - D2[dst[p]])) — one block per edge
__global__ void __launch_bounds__(256)
k_edge_act(const float* __restrict__ C, const float* __restrict__ D) {
    int p = blockIdx.x;
    int s = g_srcs[p], d = g_dsts[p];
    int t = threadIdx.x;
    const float4 cv = *(const float4*)(C + (size_t)s * 1024 + t * 4);
    const float4 dv = *(const float4*)(D + (size_t)d * 1024 + t * 4);
    float m0 = leaky1f(cv.x - dv.x), m1 = leaky1f(cv.y - dv.y);
    float m2 = leaky1f(cv.z - dv.z), m3 = leaky1f(cv.w - dv.w);
    __half h0 = __float2half(m0), h1 = __float2half(m1);
    __half h2 = __float2half(m2), h3 = __float2half(m3);
    __half* base = g_ACT + (size_t)p * 2048 + t * 4;
    *(__half2*)(base) = __halves2half2(h0, h1);
    *(__half2*)(base + 2) = __halves2half2(h2, h3);
    *(__half2*)(base + 1024) = __halves2half2(__float2half(m0 - __half2float(h0)),
                                              __float2half(m1 - __half2float(h1)));
    *(__half2*)(base + 1026) = __halves2half2(__float2half(m2 - __half2float(h2)),
                                              __float2half(m3 - __half2float(h3)));
}

// agg fp32 -> hi/lo pair buffer [NN, 2F]
__global__ void k_fin_hl(const float* __restrict__ agg, __half* __restrict__ out,
                         int logF, int total) {
    int idx = blockIdx.x * blockDim.x + threadIdx.x;
    if (idx >= total) return;
    int F = 1 << logF;
    int n = idx >> logF, f = idx & (F - 1);
    float v = agg[idx];
    if (v < -1e30f) v = 0.0f;
    __half hi = __float2half(v);
    out[(size_t)n * 2 * F + f] = hi;
    out[(size_t)n * 2 * F + F + f] = __float2half(v - __half2float(hi));
}

// two-stage deterministic BN stats
__global__ void k_stats_partial(const float* __restrict__ P, int F) {
    int c = blockIdx.x * 128 + threadIdx.x;
    int r0 = blockIdx.y * 128;
    int r1 = r0 + 128; if (r1 > NN) r1 = NN;
    float s = 0.f, q = 0.f;
    for (int r = r0; r < r1; r++) {
        float v = P[(size_t)r * F + c];
        s += v; q += v * v;
    }
    g_part[(size_t)blockIdx.y * F + c] = s;
    g_partq[(size_t)blockIdx.y * F + c] = q;
}

__global__ void k_stats_final(int F) {
    int c = blockIdx.x * 128 + threadIdx.x;
    if (c >= F) return;
    float s = 0.f, q = 0.f;
    for (int t = 0; t < MTILES; t++) {
        s += g_part[(size_t)t * F + c];
        q += g_partq[(size_t)t * F + c];
    }
    float mu = s / NN;
    float var = fmaxf(q / NN - mu * mu, 0.0f);
    g_mu[c] = mu;
    g_rs[c] = rsqrtf(var + 1e-5f);
}

// BN -> hi/lo pair buffer
__global__ void k_norm_hl(const float* __restrict__ P, const float* __restrict__ gamma,
                          const float* __restrict__ beta, __half* __restrict__ out,
                          int logF, int total) {
    int idx = blockIdx.x * blockDim.x + threadIdx.x;
    if (idx >= total) return;
    int F = 1 << logF;
    int n = idx >> logF, f = idx & (F - 1);
    float v = gamma[f] * (P[idx] - g_mu[f]) * g_rs[f] + beta[f];
    __half hi = __float2half(v);
    out[(size_t)n * 2 * F + f] = hi;
    out[(size_t)n * 2 * F + F + f] = __float2half(v - __half2float(hi));
}

__global__ void k_norm_float(const float* __restrict__ P, const float* __restrict__ gamma,
                             const float* __restrict__ beta, float* __restrict__ out,
                             int mask, int total) {
    int idx = blockIdx.x * blockDim.x + threadIdx.x;
    if (idx < total) {
        int f = idx & mask;
        out[idx] = gamma[f] * (P[idx] - g_mu[f]) * g_rs[f] + beta[f];
    }
}

// ------------------------- node GEMM (3-slot, single-sync pipeline) -------------------------
#define NSTG 61440
#define NSMEM (3 * NSTG + 128)

template <int KB, int MODE>
__global__ void __launch_bounds__(512, 1)
k_ngemm(const __half* __restrict__ A, const __half* __restrict__ Wt,
        const float* __restrict__ bias, __half* __restrict__ outH,
        float* __restrict__ outF, const float* __restrict__ extra, int M) {
    extern __shared__ char dsm_raw[];
    char* dsm0 = (char*)(((uintptr_t)dsm_raw + 127) & ~(uintptr_t)127);
    const uint32_t sb0 = smem_u32(dsm0);

    const int tid = threadIdx.x;
    const int wid = tid >> 5;
    const int lane = tid & 31;
    const int wm = wid & 1, wn = wid >> 1;
    const int tileM = blockIdx.x;
    const int colg0 = blockIdx.y * 256;
    const int F = gridDim.y * 256;
    constexpr int NCH = KB / 32;

    auto load_chunk = [&](int ch) {
        const int k0 = ch * 32;
        const uint32_t sb = sb0 + (ch % 3) * NSTG;
        int r = tid >> 2, s = tid & 3;
        int rg = tileM * 128 + r;
        if (rg >= M) rg = M - 1;
        const __half* asrc = A + (size_t)rg * 2 * KB + k0 + s * 8;
        cp16(sb + r * 80 + s * 16, asrc);
        cp16(sb + 10240 + r * 80 + s * 16, asrc + KB);
#pragma unroll
        for (int i = 0; i < 2; i++) {
            int idx = tid + i * 512;
            int wr = idx >> 2, ws_ = idx & 3;
            const __half* wsrc = Wt + (size_t)(colg0 + wr) * 2 * KB + k0 + ws_ * 8;
            cp16(sb + 20480 + wr * 80 + ws_ * 16, wsrc);
            cp16(sb + 40960 + wr * 80 + ws_ * 16, wsrc + KB);
        }
        cp_commit();
    };

    float c[4][4][4];
#pragma unroll
    for (int i = 0; i < 4; i++)
#pragma unroll
        for (int j = 0; j < 4; j++)
#pragma unroll
            for (int k = 0; k < 4; k++) c[i][j][k] = 0.0f;

    load_chunk(0);

#pragma unroll 1
    for (int ch = 0; ch < NCH; ch++) {
        if (ch + 1 < NCH) {
            load_chunk(ch + 1);
            cp_wait1();
        } else {
            cp_wait0();
        }
        __syncthreads();
        __half* Ah = (__half*)(dsm0 + (ch % 3) * NSTG);
        __half* Al = Ah + 5120;
        __half* Bh = Ah + 10240;
        __half* Bl = Ah + 20480;
        mma_chunk_abb(Ah, Bh, Bl, lane, wm, wn, c);
        mma_chunk(Al, Bh, lane, wm, wn, c);
    }

#pragma unroll
    for (int mf = 0; mf < 4; mf++) {
#pragma unroll
        for (int nf = 0; nf < 4; nf++) {
            int rl = wm * 64 + mf * 16 + (lane >> 2);
            int cl = wn * 32 + nf * 8 + (lane & 3) * 2;
            int cg = colg0 + cl;
            float b0 = bias[cg], b1 = bias[cg + 1];
#pragma unroll
            for (int h = 0; h < 2; h++) {
                int rg = tileM * 128 + rl + h * 8;
                if (rg >= M) continue;
                float v0 = c[mf][nf][2 * h + 0] + b0;
                float v1 = c[mf][nf][2 * h + 1] + b1;
                if (MODE == 0) {
                    v0 = leaky1f(v0); v1 = leaky1f(v1);
                    __half h0 = __float2half(v0), h1 = __float2half(v1);
                    *(__half2*)&outH[(size_t)rg * 2 * F + cg] = __halves2half2(h0, h1);
                    *(__half2*)&outH[(size_t)rg * 2 * F + F + cg] = __halves2half2(
                        __float2half(v0 - __half2float(h0)), __float2half(v1 - __half2float(h1)));
                } else if (MODE == 1) {
                    v0 = leaky1f(leaky1f(v0)); v1 = leaky1f(leaky1f(v1));
                    *(float2*)&outF[(size_t)rg * F + cg] = make_float2(v0, v1);
                } else {
                    float2 ex = *(const float2*)&extra[(size_t)rg * F + cg];
                    *(float2*)&outF[(size_t)rg * F + cg] = make_float2(v0 + ex.x, v1 + ex.y);
                }
            }
        }
    }
}

// ------------------------- legacy edge GEMM (conv1, small) -------------------------
template <int KB, int NWN>
__global__ void __launch_bounds__(NWN * 64, 1)
k_edge_gemm(const float* __restrict__ Crow, const float* __restrict__ Drow,
            const __half* __restrict__ Wt, const float* __restrict__ bias,
            float* __restrict__ agg) {
    constexpr int NT = NWN * 32;
    constexpr int T = NWN * 64;
    extern __shared__ __align__(16) char dsm[];
    __half* As_hi = (__half*)dsm;
    __half* As_lo = As_hi + 128 * 40;
    __half* Bs_hi = As_lo + 128 * 40;
    __half* Bs_lo = Bs_hi + NT * 40;
    float* Cs = (float*)dsm;
    __shared__ int s_src[128];
    __shared__ int s_dst[128];

    const int tid = threadIdx.x;
    const int lane = tid & 31;
    const int warp = tid >> 5;
    const int wm = warp & 1, wn = warp >> 1;
    const int e0 = blockIdx.x * 128;
    const int colg0 = blockIdx.y * NT;
    const int F = gridDim.y * NT;

    if (tid < 128) {
        s_src[tid] = g_srcs[e0 + tid];
        s_dst[tid] = g_dsts[e0 + tid];
    }
    __syncthreads();

    float c[4][4][4];
#pragma unroll
    for (int i = 0; i < 4; i++)
#pragma unroll
        for (int j = 0; j < 4; j++)
#pragma unroll
            for (int k = 0; k < 4; k++) c[i][j][k] = 0.0f;

    for (int k0 = 0; k0 < KB; k0 += 32) {
#pragma unroll
        for (int i = 0; i < 1024 / T; i++) {
            int idx = tid + i * T;
            int r = idx >> 3, s = idx & 7;
            const float4 cv = *(const float4*)(Crow + (size_t)s_src[r] * KB + k0 + s * 4);
            const float4 dv = *(const float4*)(Drow + (size_t)s_dst[r] * KB + k0 + s * 4);
            float m0 = leaky1f(cv.x - dv.x), m1 = leaky1f(cv.y - dv.y);
            float m2 = leaky1f(cv.z - dv.z), m3 = leaky1f(cv.w - dv.w);
            __half h0 = __float2half(m0), h1 = __float2half(m1);
            __half h2 = __float2half(m2), h3 = __float2half(m3);
            int off = r * 40 + s * 4;
            *(__half2*)&As_hi[off] = __halves2half2(h0, h1);
            *(__half2*)&As_hi[off + 2] = __halves2half2(h2, h3);
            *(__half2*)&As_lo[off] = __halves2half2(__float2half(m0 - __half2float(h0)),
                                                    __float2half(m1 - __half2float(h1)));
            *(__half2*)&As_lo[off + 2] = __halves2half2(__float2half(m2 - __half2float(h2)),
                                                        __float2half(m3 - __half2float(h3)));
        }
#pragma unroll
        for (int i = 0; i < NT * 4 / T; i++) {
            int idx = tid + i * T;
            int r = idx >> 2, s = idx & 3;
            const __half* wrow = Wt + (size_t)(colg0 + r) * 2 * KB + k0 + s * 8;
            *(int4*)&Bs_hi[r * 40 + s * 8] = *(const int4*)wrow;
            *(int4*)&Bs_lo[r * 40 + s * 8] = *(const int4*)(wrow + KB);
        }
        __syncthreads();
        mma_chunk_abb(As_hi, Bs_hi, Bs_lo, lane, wm, wn, c);
        mma_chunk(As_lo, Bs_hi, lane, wm, wn, c);
        __syncthreads();
    }

#pragma unroll
    for (int mf = 0; mf < 4; mf++) {
#pragma unroll
        for (int nf = 0; nf < 4; nf++) {
            int rl = wm * 64 + mf * 16 + (lane >> 2);
            int cl = wn * 32 + nf * 8 + (lane & 3) * 2;
            float b0 = bias[colg0 + cl], b1 = bias[colg0 + cl + 1];
#pragma unroll
            for (int h = 0; h < 2; h++) {
                float v0 = leaky1f(c[mf][nf][2 * h + 0] + b0);
                float v1 = leaky1f(c[mf][nf][2 * h + 1] + b1);
                *(float2*)&Cs[(rl + h * 8) * (NT + 2) + cl] = make_float2(v0, v1);
            }
        }
    }
    __syncthreads();

    {
        int col = tid & (NT - 1);
        int rbeg = (tid >= NT) ? 64 : 0;
        float cur = __int_as_float(0xff800000);
        int curd = s_dst[rbeg];
        for (int r = rbeg; r < rbeg + 64; r++) {
            int d = s_dst[r];
            if (d != curd) {
                atomicMaxF(&agg[(size_t)curd * F + colg0 + col], cur);
                cur = __int_as_float(0xff800000);
                curd = d;
            }
            cur = fmaxf(cur, Cs[r * (NT + 2) + col]);
        }
        atomicMaxF(&agg[(size_t)curd * F + colg0 + col], cur);
    }
}

// ------------------------- conv2 edge GEMM: tcgen05, M=256 shared-W, 2-ahead pipeline -------------------------
// 512 threads, tile 256 edges x 256 cols. Slot = A0(hi/lo 16KB) + A1(hi/lo 16KB) + W(hi/lo 32KB) = 64KB.
// 3 slots, 2-ahead pipelined cp.async, mbar-guarded slot reuse, two 256-col TMEM accumulators.
#define EK_SLOT 65536
#define EK_SMEM (3 * EK_SLOT + 1024)
#define LSTG    61440

__global__ void __launch_bounds__(512, 1)
k_edge_tc(const float* __restrict__ bias, float* __restrict__ agg) {
    extern __shared__ char dsm_raw[];
    char* dsm0 = (char*)(((uintptr_t)dsm_raw + 1023) & ~(uintptr_t)1023);
    __shared__ int s_dst[256];

    const int tid = threadIdx.x;
    const int wid = tid >> 5;
    const int lane = tid & 31;
    const int e0 = blockIdx.x * 256;
    const int y = blockIdx.y;
    const int colg0 = y * 256;

    if (tid < 256) s_dst[tid] = g_dsts[e0 + tid];

    float* Cs = (float*)dsm0;  // 128 x 258 fp32 per tile pass

#if HAS_TC
    // ================= tcgen05 path (live) =================
    __shared__ __align__(8) uint64_t s_mbar[3];
    __shared__ uint32_t s_tmem;
    const uint32_t sbase = smem_u32(dsm0);

    if (tid == 0) {
        mbar_init(smem_u32(&s_mbar[0]), 1);
        mbar_init(smem_u32(&s_mbar[1]), 1);
        mbar_init(smem_u32(&s_mbar[2]), 1);
    }
    if (wid == 0) {
        asm volatile("tcgen05.alloc.cta_group::1.sync.aligned.shared::cta.b32 [%0], %1;"
                     :: "r"(smem_u32(&s_tmem)), "r"(512u) : "memory");
    }
    __syncthreads();
    const uint32_t tmem = s_tmem;

    const uint32_t IDESC = (1u << 4) | (32u << 17) | (8u << 24);  // f32, f16xf16, N=256, M=128
    int wp[3] = {0, 0, 0};

    auto load_chunk = [&](int ch) {
        const uint32_t su = sbase + (ch % 3) * EK_SLOT;
        const int k0h = ch * 32;
        int r = tid >> 2, s = tid & 3;
        uint32_t bo = (uint32_t)(r * 64 + s * 16);
        uint32_t sw = bo ^ ((bo >> 3) & 0x30);
#pragma unroll
        for (int t = 0; t < 2; t++) {
            const __half* src = g_ACT + (size_t)(e0 + t * 128 + r) * 2048 + k0h + s * 8;
            cp16(su + t * 16384 + sw, src);
            cp16(su + t * 16384 + 8192 + sw, src + 1024);
        }
        const char* ws = (const char*)(g_W2sw + (size_t)(y * 32 + ch) * 16384);
#pragma unroll
        for (int i = 0; i < 4; i++) {
            int j = tid + i * 512;
            cp16(su + 32768 + j * 16, ws + j * 16);
        }
        cp_commit();
    };

    load_chunk(0);
    load_chunk(1);

#pragma unroll 1
    for (int ch = 0; ch < 32; ch++) {
        if (ch + 2 < 32) {
            int c = ch + 2, sl = c % 3;
            if (c >= 3) { mbar_wait(smem_u32(&s_mbar[sl]), wp[sl] & 1); wp[sl]++; }
            load_chunk(c);
            cp_wait2();
        } else if (ch + 1 < 32) {
            cp_wait1();
        } else {
            cp_wait0();
        }
        asm volatile("fence.proxy.async.shared::cta;" ::: "memory");
        __syncthreads();
        if (wid == 0 && elect_one_pred()) {
            const uint32_t su = sbase + (ch % 3) * EK_SLOT;
            uint64_t a0h = make_desc64(su);
            uint64_t a0l = make_desc64(su + 8192);
            uint64_t a1h = make_desc64(su + 16384);
            uint64_t a1l = make_desc64(su + 24576);
            uint64_t wh  = make_desc64(su + 32768);
            uint64_t wl  = make_desc64(su + 49152);
#pragma unroll
            for (int ks = 0; ks < 2; ks++) {
                uint32_t en = (ch == 0 && ks == 0) ? 0u : 1u;
                mma_f16_ss_cg1(tmem,       a0h + ks * 2, wh + ks * 2, IDESC, en);
                mma_f16_ss_cg1(tmem,       a0l + ks * 2, wh + ks * 2, IDESC, 1u);
                mma_f16_ss_cg1(tmem,       a0h + ks * 2, wl + ks * 2, IDESC, 1u);
                mma_f16_ss_cg1(tmem + 256, a1h + ks * 2, wh + ks * 2, IDESC, en);
                mma_f16_ss_cg1(tmem + 256, a1l + ks * 2, wh + ks * 2, IDESC, 1u);
                mma_f16_ss_cg1(tmem + 256, a1h + ks * 2, wl + ks * 2, IDESC, 1u);
            }
            asm volatile(
                "tcgen05.commit.cta_group::1.mbarrier::arrive::one.shared::cluster.b64 [%0];"
                :: "r"(smem_u32(&s_mbar[ch % 3])) : "memory");
        }
    }
    mbar_wait(smem_u32(&s_mbar[0]), wp[0] & 1);
    mbar_wait(smem_u32(&s_mbar[1]), wp[1] & 1);
    mbar_wait(smem_u32(&s_mbar[2]), wp[2] & 1);
    asm volatile("tcgen05.fence::after_thread_sync;" ::: "memory");
    __syncthreads();

#pragma unroll 1
    for (int t = 0; t < 2; t++) {
        if (wid < 4) {
            int row = wid * 32 + lane;
#pragma unroll 1
            for (int cc = 0; cc < 8; cc++) {
                uint32_t regs[32];
                asm volatile(
                    "tcgen05.ld.sync.aligned.32x32b.x32.b32 "
                    "{%0,%1,%2,%3,%4,%5,%6,%7,%8,%9,%10,%11,%12,%13,%14,%15,"
                    "%16,%17,%18,%19,%20,%21,%22,%23,%24,%25,%26,%27,%28,%29,%30,%31}, [%32];"
                    : "=r"(regs[0]), "=r"(regs[1]), "=r"(regs[2]), "=r"(regs[3]),
                      "=r"(regs[4]), "=r"(regs[5]), "=r"(regs[6]), "=r"(regs[7]),
                      "=r"(regs[8]), "=r"(regs[9]), "=r"(regs[10]), "=r"(regs[11]),
                      "=r"(regs[12]), "=r"(regs[13]), "=r"(regs[14]), "=r"(regs[15]),
                      "=r"(regs[16]), "=r"(regs[17]), "=r"(regs[18]), "=r"(regs[19]),
                      "=r"(regs[20]), "=r"(regs[21]), "=r"(regs[22]), "=r"(regs[23]),
                      "=r"(regs[24]), "=r"(regs[25]), "=r"(regs[26]), "=r"(regs[27]),
                      "=r"(regs[28]), "=r"(regs[29]), "=r"(regs[30]), "=r"(regs[31])
                    : "r"(tmem + t * 256 + cc * 32));
                asm volatile("tcgen05.wait::ld.sync.aligned;" ::: "memory");
#pragma unroll
                for (int j = 0; j < 32; j++) {
                    int col = cc * 32 + j;
                    Cs[row * 258 + col] = leaky1f(__uint_as_float(regs[j]) + bias[colg0 + col]);
                }
            }
            asm volatile("tcgen05.fence::before_thread_sync;" ::: "memory");
        }
        __syncthreads();
        {
            int col = tid & 255;
            int rbeg = (tid >= 256) ? 64 : 0;
            float cur = __int_as_float(0xff800000);
            int curd = s_dst[t * 128 + rbeg];
#pragma unroll 1
            for (int r = rbeg; r < rbeg + 64; r++) {
                int d = s_dst[t * 128 + r];
                if (d != curd) {
                    atomicMaxF(&agg[(size_t)curd * 1024 + colg0 + col], cur);
                    cur = __int_as_float(0xff800000);
                    curd = d;
                }
                cur = fmaxf(cur, Cs[r * 258 + col]);
            }
            atomicMaxF(&agg[(size_t)curd * 1024 + colg0 + col], cur);
        }
        __syncthreads();
    }

    if (wid == 0) {
        asm volatile("tcgen05.relinquish_alloc_permit.cta_group::1.sync.aligned;");
        asm volatile("tcgen05.dealloc.cta_group::1.sync.aligned.b32 %0, %1;"
                     :: "r"(tmem), "r"(512u));
    }
#else
    // ================= legacy mma.sync fallback: two 128-edge tiles sequentially =================
    const int wm = wid & 1, wn = wid >> 1;
    const uint32_t sb0 = smem_u32(dsm0);

#pragma unroll 1
    for (int t = 0; t < 2; t++) {
        __syncthreads();
        float c[4][4][4];
#pragma unroll
        for (int i = 0; i < 4; i++)
#pragma unroll
            for (int j = 0; j < 4; j++)
#pragma unroll
                for (int k = 0; k < 4; k++) c[i][j][k] = 0.0f;

        auto load_chunk = [&](int ch) {
            const int k0 = ch * 32;
            const uint32_t sb = sb0 + (ch % 3) * LSTG;
            int r = tid >> 2, s = tid & 3;
            const __half* asrc = g_ACT + (size_t)(e0 + t * 128 + r) * 2048 + k0 + s * 8;
            cp16(sb + r * 80 + s * 16, asrc);
            cp16(sb + 10240 + r * 80 + s * 16, asrc + 1024);
#pragma unroll
            for (int i = 0; i < 2; i++) {
                int idx = tid + i * 512;
                int wr = idx >> 2, ws_ = idx & 3;
                const __half* wsrc = g_W_l2w2 + (size_t)(colg0 + wr) * 2048 + k0 + ws_ * 8;
                cp16(sb + 20480 + wr * 80 + ws_ * 16, wsrc);
                cp16(sb + 40960 + wr * 80 + ws_ * 16, wsrc + 1024);
            }
            cp_commit();
        };

        load_chunk(0);
#pragma unroll 1
        for (int ch = 0; ch < 32; ch++) {
            if (ch + 1 < 32) { load_chunk(ch + 1); cp_wait1(); }
            else             { cp_wait0(); }
            __syncthreads();
            __half* Ah = (__half*)(dsm0 + (ch % 3) * LSTG);
            __half* Al = Ah + 5120;
            __half* Bh = Ah + 10240;
            __half* Bl = Ah + 20480;
            mma_chunk_abb(Ah, Bh, Bl, lane, wm, wn, c);
            mma_chunk(Al, Bh, lane, wm, wn, c);
        }
        __syncthreads();

#pragma unroll
        for (int mf = 0; mf < 4; mf++) {
#pragma unroll
            for (int nf = 0; nf < 4; nf++) {
                int rl = wm * 64 + mf * 16 + (lane >> 2);
                int cl = wn * 32 + nf * 8 + (lane & 3) * 2;
                float b0 = bias[colg0 + cl], b1 = bias[colg0 + cl + 1];
#pragma unroll
                for (int h = 0; h < 2; h++) {
                    float v0 = leaky1f(c[mf][nf][2 * h + 0] + b0);
                    float v1 = leaky1f(c[mf][nf][2 * h + 1] + b1);
                    *(float2*)&Cs[(rl + h * 8) * 258 + cl] = make_float2(v0, v1);
                }
            }
        }
        __syncthreads();
        {
            int col = tid & 255;
            int rbeg = (tid >= 256) ? 64 : 0;
            float cur = __int_as_float(0xff800000);
            int curd = s_dst[t * 128 + rbeg];
#pragma unroll 1
            for (int r = rbeg; r < rbeg + 64; r++) {
                int d = s_dst[t * 128 + r];
                if (d != curd) {
                    atomicMaxF(&agg[(size_t)curd * 1024 + colg0 + col], cur);
                    cur = __int_as_float(0xff800000);
                    curd = d;
                }
                cur = fmaxf(cur, Cs[r * 258 + col]);
            }
            atomicMaxF(&agg[(size_t)curd * 1024 + colg0 + col], cur);
        }
        __syncthreads();
    }
#endif
}

// ------------------------- host -------------------------
static void* sym(const void* s) {
    void* p = nullptr;
    cudaGetSymbolAddress(&p, s);
    return p;
}

extern "C" void kernel_launch(void* const* d_in, const int* in_sizes, int n_in,
                              void* d_out, int out_size) {
    const float* x    = (const float*)d_in[0];
    const int*   ei   = (const int*)d_in[1];
    const float* l1w1 = (const float*)d_in[3];
    const float* l1b1 = (const float*)d_in[4];
    const float* l1w2 = (const float*)d_in[5];
    const float* l1b2 = (const float*)d_in[6];
    const float* g1w1 = (const float*)d_in[7];
    const float* g1b1 = (const float*)d_in[8];
    const float* g1w2 = (const float*)d_in[9];
    const float* g1b2 = (const float*)d_in[10];
    const float* gamma1 = (const float*)d_in[11];
    const float* beta1  = (const float*)d_in[12];
    const float* l2w1 = (const float*)d_in[13];
    const float* l2b1 = (const float*)d_in[14];
    const float* l2w2 = (const float*)d_in[15];
    const float* l2b2 = (const float*)d_in[16];
    const float* g2w1 = (const float*)d_in[17];
    const float* g2b1 = (const float*)d_in[18];
    const float* g2w2 = (const float*)d_in[19];
    const float* g2b2 = (const float*)d_in[20];
    const float* gamma2 = (const float*)d_in[21];
    const float* beta2  = (const float*)d_in[22];

    float*  A1f    = (float*)sym(g_A1f);
    float*  B1f    = (float*)sym(g_B1f);
    float*  agg1   = (float*)sym(g_agg1);
    __half* agg1hl = (__half*)sym(g_agg1hl);
    __half* T1hl   = (__half*)sym(g_T1hl);
    float*  P1     = (float*)sym(g_P1);
    __half* H1hl   = (__half*)sym(g_H1hl);
    float*  C2f    = (float*)sym(g_C2f);
    float*  D2f    = (float*)sym(g_D2f);
    float*  agg2   = (float*)sym(g_agg2);
    __half* agg2hl = (__half*)sym(g_agg2hl);
    __half* U2hl   = (__half*)sym(g_U2hl);
    float*  P2     = (float*)sym(g_P2);
    __half* W_l1w2 = (__half*)sym(g_W_l1w2);
    __half* W_g1w1 = (__half*)sym(g_W_g1w1);
    __half* W_g1w2 = (__half*)sym(g_W_g1w2);
    __half* W_l2w1 = (__half*)sym(g_W_l2w1);
    __half* W_g2w1 = (__half*)sym(g_W_g2w1);
    __half* W_g2w2 = (__half*)sym(g_W_g2w2);

    cudaFuncSetAttribute(k_edge_gemm<64, 4>, cudaFuncAttributeMaxDynamicSharedMemorySize,
                         128 * 130 * 4);
    cudaFuncSetAttribute(k_edge_tc, cudaFuncAttributeMaxDynamicSharedMemorySize, EK_SMEM);
    cudaFuncSetAttribute(k_ngemm<128, 0>, cudaFuncAttributeMaxDynamicSharedMemorySize, NSMEM);
    cudaFuncSetAttribute(k_ngemm<256, 1>, cudaFuncAttributeMaxDynamicSharedMemorySize, NSMEM);
    cudaFuncSetAttribute(k_ngemm<512, 2>, cudaFuncAttributeMaxDynamicSharedMemorySize, NSMEM);
    cudaFuncSetAttribute(k_ngemm<1024, 0>, cudaFuncAttributeMaxDynamicSharedMemorySize, NSMEM);
    cudaFuncSetAttribute(k_ngemm<2048, 1>, cudaFuncAttributeMaxDynamicSharedMemorySize, NSMEM);

    // CSR build
    k_init<<<(NN * 1024 + 255) / 256, 256>>>();
    k_hist<<<(NE + 255) / 256, 256>>>(ei);
    k_scan<<<1, 1024>>>();
    k_scatter<<<(NE + 255) / 256, 256>>>(ei);

    // weights -> split fp16 (coalesced tiled transpose) + SW64 tcgen05 tiles (l2w2)
    dim3 tb(32, 8);
    k_cvtT_split_t<<<dim3(128 / 32, 64 / 32), tb>>>(l1w2, W_l1w2, 64, 128);
    k_cvtT_split_t<<<dim3(256 / 32, 128 / 32), tb>>>(g1w1, W_g1w1, 128, 256);
    k_cvtT_split_t<<<dim3(512 / 32, 256 / 32), tb>>>(g1w2, W_g1w2, 256, 512);
    k_cvtT_split_t<<<dim3(1024 / 32, 512 / 32), tb>>>(l2w1, W_l2w1, 512, 1024);
    k_cvtT_split_t<<<dim3(1024 / 32, 1024 / 32), tb>>>(l2w2, (__half*)sym(g_W_l2w2), 1024, 1024);
    k_cvt_w2sw<<<(1024 * 1024 + 255) / 256, 256>>>(l2w2);
    k_cvtT_split_t<<<dim3(2048 / 32, 1024 / 32), tb>>>(g2w1, W_g2w1, 1024, 2048);
    k_cvtT_split_t<<<dim3(2048 / 32, 2048 / 32), tb>>>(g2w2, W_g2w2, 2048, 2048);

    // conv1
    k_precomp1<<<(NN * 64 + 255) / 256, 256>>>(x, l1w1, l1b1);
    k_edge_gemm<64, 4><<<dim3(NE / 128, 1), 256, 128 * 130 * 4>>>(A1f, B1f, W_l1w2, l1b2, agg1);
    k_fin_hl<<<(NN * 128 + 255) / 256, 256>>>(agg1, agg1hl, 7, NN * 128);
    k_ngemm<128, 0><<<dim3(MTILES, 1), 512, NSMEM>>>(agg1hl, W_g1w1, g1b1, T1hl, nullptr, nullptr, NN);
    k_ngemm<256, 1><<<dim3(MTILES, 2), 512, NSMEM>>>(T1hl, W_g1w2, g1b2, nullptr, P1, nullptr, NN);
    k_stats_partial<<<dim3(4, MTILES), 128>>>(P1, 512);
    k_stats_final<<<4, 128>>>(512);
    k_norm_hl<<<(NN * 512 + 255) / 256, 256>>>(P1, gamma1, beta1, H1hl, 9, NN * 512);

    // conv2
    k_precompD2<<<(NN * 1024 + 255) / 256, 256>>>(x, l2w1);
    k_ngemm<512, 2><<<dim3(MTILES, 4), 512, NSMEM>>>(H1hl, W_l2w1, l2b1, nullptr, C2f, D2f, NN);
    k_edge_act<<<NE, 256>>>(C2f, D2f);
    k_edge_tc<<<dim3(NE / 256, 4), 512, EK_SMEM>>>(l2b2, agg2);
    k_fin_hl<<<(NN * 1024 + 255) / 256, 256>>>(agg2, agg2hl, 10, NN * 1024);
    k_ngemm<1024, 0><<<dim3(MTILES, 8), 512, NSMEM>>>(agg2hl, W_g2w1, g2b1, U2hl, nullptr, nullptr, NN);
    k_ngemm<2048, 1><<<dim3(MTILES, 8), 512, NSMEM>>>(U2hl, W_g2w2, g2b2, nullptr, P2, nullptr, NN);
    k_stats_partial<<<dim3(16, MTILES), 128>>>(P2, 2048);
    k_stats_final<<<16, 128>>>(2048);
    k_norm_float<<<(NN * 2048 + 255) / 256, 256>>>(P2, gamma2, beta2, (float*)d_out, 2047,
                                                   NN * 2048);
}

// round 16
// speedup vs baseline: 1.3566x; 1.3566x over previous
#include <cuda_runtime.h>
#include <cuda_fp16.h>
#include <stdint.h>

#define NN 10000
#define NE 160000
#define MTILES 79  // ceil(10000/128)

#if defined(__CUDA_ARCH_FEAT_SM103_ALL) || defined(__CUDA_ARCH_FEAT_SM100_ALL)
#define HAS_TC 1
#else
#define HAS_TC 0
#endif

// ------------------------- device scratch -------------------------
__device__ int g_deg[NN];
__device__ int g_cur[NN];
__device__ int g_srcs[NE];
__device__ int g_dsts[NE];

__device__ float  g_A1f[NN * 64];
__device__ float  g_B1f[NN * 64];
__device__ float  g_agg1[NN * 128];
__device__ __half g_agg1hl[NN * 256];
__device__ __half g_T1hl[NN * 512];
__device__ float  g_P1[NN * 512];
__device__ __half g_H1hl[NN * 1024];
__device__ float  g_C2f[NN * 1024];
__device__ float  g_D2f[NN * 1024];
__device__ float  g_agg2[NN * 1024];
__device__ __half g_agg2hl[NN * 2048];
__device__ __half g_U2hl[NN * 4096];
__device__ float  g_P2[NN * 2048];
__device__ float  g_mu[2048];
__device__ float  g_rs[2048];
__device__ float  g_part[MTILES * 2048];
__device__ float  g_partq[MTILES * 2048];

// edge activations (CSR order): [p][0,1024)=hi, [1024,2048)=lo
__device__ __half g_ACT[(size_t)NE * 2048];

// split weights, layout [F, 2K]: [0,K)=hi, [K,2K)=lo (legacy mma kernels)
__device__ __half g_W_l1w2[128 * 128];
__device__ __half g_W_g1w1[256 * 256];
__device__ __half g_W_g1w2[512 * 512];
__device__ __half g_W_l2w1[1024 * 1024];
__device__ __half g_W_l2w2[1024 * 2048];
__device__ __half g_W_g2w1[2048 * 2048];
__device__ __half g_W_g2w2[2048 * 4096];

// SW64-swizzled tcgen05 weight tiles: [y(F/256)][ch(K/32)][hi 8192 | lo 8192] halves,
// tile = 256 rows x 32 halves (64B rows).
__device__ __half g_W2sw[4 * 32 * 16384];       // l2w2  K=1024 F=1024
__device__ __half g_Wsw_l2w1[4 * 16 * 16384];   // l2w1  K=512  F=1024
__device__ __half g_Wsw_g2w1[8 * 32 * 16384];   // g2w1  K=1024 F=2048
__device__ __half g_Wsw_g2w2[8 * 64 * 16384];   // g2w2  K=2048 F=2048

// ------------------------- helpers -------------------------
__device__ __forceinline__ float leaky1f(float v) { return v > 0.0f ? v : 0.05f * v; }

__device__ __forceinline__ void atomicMaxF(float* addr, float v) {
    if (v >= 0.0f) atomicMax((int*)addr, __float_as_int(v));
    else           atomicMin((unsigned int*)addr, (unsigned int)__float_as_int(v));
}

__device__ __forceinline__ uint32_t smem_u32(const void* p) {
    return (uint32_t)__cvta_generic_to_shared(p);
}

__device__ __forceinline__ void cp16(uint32_t dst, const void* src) {
    asm volatile("cp.async.cg.shared.global [%0], [%1], 16;" :: "r"(dst), "l"(src));
}
__device__ __forceinline__ void cp_commit() {
    asm volatile("cp.async.commit_group;" ::: "memory");
}
__device__ __forceinline__ void cp_wait0() {
    asm volatile("cp.async.wait_group 0;" ::: "memory");
}
__device__ __forceinline__ void cp_wait1() {
    asm volatile("cp.async.wait_group 1;" ::: "memory");
}

// ---- legacy mma.sync path ----
__device__ __forceinline__ void ldsm_x4(uint32_t& r0, uint32_t& r1, uint32_t& r2, uint32_t& r3,
                                        uint32_t addr) {
    asm volatile("ldmatrix.sync.aligned.m8n8.x4.shared.b16 {%0,%1,%2,%3}, [%4];"
                 : "=r"(r0), "=r"(r1), "=r"(r2), "=r"(r3) : "r"(addr));
}

__device__ __forceinline__ void mma16816(float c[4], const uint32_t a[4], const uint32_t b[2]) {
    asm volatile(
        "mma.sync.aligned.m16n8k16.row.col.f32.f16.f16.f32 "
        "{%0,%1,%2,%3},{%4,%5,%6,%7},{%8,%9},{%0,%1,%2,%3};"
        : "+f"(c[0]), "+f"(c[1]), "+f"(c[2]), "+f"(c[3])
        : "r"(a[0]), "r"(a[1]), "r"(a[2]), "r"(a[3]), "r"(b[0]), "r"(b[1]));
}

// standard chunk: one A x one B over K=32
__device__ __forceinline__ void mma_chunk(const __half* As, const __half* Bs, int lane,
                                          int wm, int wn, float c[4][4][4]) {
#pragma unroll
    for (int ks = 0; ks < 2; ks++) {
        const int k0 = ks * 16;
        uint32_t a[4][4];
#pragma unroll
        for (int mf = 0; mf < 4; mf++) {
            const __half* ap = As + (wm * 64 + mf * 16 + (lane & 15)) * 40 + k0 + ((lane >> 4) << 3);
            ldsm_x4(a[mf][0], a[mf][1], a[mf][2], a[mf][3], smem_u32(ap));
        }
        uint32_t b[4][2];
#pragma unroll
        for (int p = 0; p < 2; p++) {
            const __half* bp = Bs + (wn * 32 + p * 16 + (lane & 7) + ((lane >> 4) << 3)) * 40
                               + k0 + (((lane >> 3) & 1) << 3);
            uint32_t r0, r1, r2, r3;
            ldsm_x4(r0, r1, r2, r3, smem_u32(bp));
            b[2 * p][0] = r0; b[2 * p][1] = r1; b[2 * p + 1][0] = r2; b[2 * p + 1][1] = r3;
        }
#pragma unroll
        for (int mf = 0; mf < 4; mf++)
#pragma unroll
            for (int nf = 0; nf < 4; nf++)
                mma16816(c[mf][nf], a[mf], b[nf]);
    }
}

// fused chunk: A-fragments loaded ONCE, used against Bh and Bl
__device__ __forceinline__ void mma_chunk_abb(const __half* As, const __half* Bh_,
                                              const __half* Bl_, int lane, int wm, int wn,
                                              float c[4][4][4]) {
#pragma unroll
    for (int ks = 0; ks < 2; ks++) {
        const int k0 = ks * 16;
        uint32_t a[4][4];
#pragma unroll
        for (int mf = 0; mf < 4; mf++) {
            const __half* ap = As + (wm * 64 + mf * 16 + (lane & 15)) * 40 + k0 + ((lane >> 4) << 3);
            ldsm_x4(a[mf][0], a[mf][1], a[mf][2], a[mf][3], smem_u32(ap));
        }
        uint32_t bh[4][2], bl[4][2];
#pragma unroll
        for (int p = 0; p < 2; p++) {
            int boff = (wn * 32 + p * 16 + (lane & 7) + ((lane >> 4) << 3)) * 40
                       + k0 + (((lane >> 3) & 1) << 3);
            uint32_t r0, r1, r2, r3;
            ldsm_x4(r0, r1, r2, r3, smem_u32(Bh_ + boff));
            bh[2 * p][0] = r0; bh[2 * p][1] = r1; bh[2 * p + 1][0] = r2; bh[2 * p + 1][1] = r3;
            ldsm_x4(r0, r1, r2, r3, smem_u32(Bl_ + boff));
            bl[2 * p][0] = r0; bl[2 * p][1] = r1; bl[2 * p + 1][0] = r2; bl[2 * p + 1][1] = r3;
        }
#pragma unroll
        for (int mf = 0; mf < 4; mf++)
#pragma unroll
            for (int nf = 0; nf < 4; nf++)
                mma16816(c[mf][nf], a[mf], bh[nf]);
#pragma unroll
        for (int mf = 0; mf < 4; mf++)
#pragma unroll
            for (int nf = 0; nf < 4; nf++)
                mma16816(c[mf][nf], a[mf], bl[nf]);
    }
}

#if HAS_TC
// ---- tcgen05 helpers (arch-specific pass only) ----
__device__ __forceinline__ uint32_t elect_one_pred() {
    uint32_t pred;
    asm volatile(
        "{\n\t.reg .pred p;\n\telect.sync _|p, 0xFFFFFFFF;\n\t"
        "selp.b32 %0, 1, 0, p;\n\t}" : "=r"(pred));
    return pred;
}

// SW64 K-major descriptor: layout=4, version=1 (Blackwell), SBO=32, LBO=1
static constexpr uint64_t SMEM_DESC_BASE_SW64 =
    (uint64_t(4) << 61) | (uint64_t(1) << 46) | (uint64_t(32) << 32) | (uint64_t(1) << 16);

__device__ __forceinline__ uint64_t make_desc64(uint32_t addr) {
    return SMEM_DESC_BASE_SW64 | ((uint64_t)(addr >> 4) & 0x3FFF);
}

__device__ __forceinline__ void mma_f16_ss_cg1(uint32_t d_tmem, uint64_t a_desc, uint64_t b_desc,
                                               uint32_t idesc, uint32_t en) {
    asm volatile(
        "{\n\t.reg .pred p;\n\tsetp.ne.u32 p, %5, 0;\n\t"
        "tcgen05.mma.cta_group::1.kind::f16 [%0], %1, %2, %3, {%4,%4,%4,%4}, p;\n\t}"
        :: "r"(d_tmem), "l"(a_desc), "l"(b_desc), "r"(idesc), "r"(0u), "r"(en)
        : "memory");
}

__device__ __forceinline__ void mbar_init(uint32_t addr, uint32_t cnt) {
    asm volatile("mbarrier.init.shared.b64 [%0], %1;" :: "r"(addr), "r"(cnt) : "memory");
}

__device__ __forceinline__ void mbar_wait(uint32_t addr, uint32_t parity) {
    asm volatile(
        "{\n\t.reg .pred P1;\n\t"
        "WAIT_%=:\n\t"
        "mbarrier.try_wait.parity.acquire.cta.shared::cta.b64 P1, [%0], %1, 0x989680;\n\t"
        "@P1 bra.uni DONE_%=;\n\t"
        "bra.uni WAIT_%=;\n\t"
        "DONE_%=:\n\t}"
        :: "r"(addr), "r"(parity) : "memory");
}

// TMEM 32x32b.x32 load into regs[32]
#define LDTM32(regs, addr)                                                              \
    asm volatile(                                                                       \
        "tcgen05.ld.sync.aligned.32x32b.x32.b32 "                                       \
        "{%0,%1,%2,%3,%4,%5,%6,%7,%8,%9,%10,%11,%12,%13,%14,%15,"                       \
        "%16,%17,%18,%19,%20,%21,%22,%23,%24,%25,%26,%27,%28,%29,%30,%31}, [%32];"      \
        : "=r"(regs[0]), "=r"(regs[1]), "=r"(regs[2]), "=r"(regs[3]),                   \
          "=r"(regs[4]), "=r"(regs[5]), "=r"(regs[6]), "=r"(regs[7]),                   \
          "=r"(regs[8]), "=r"(regs[9]), "=r"(regs[10]), "=r"(regs[11]),                 \
          "=r"(regs[12]), "=r"(regs[13]), "=r"(regs[14]), "=r"(regs[15]),               \
          "=r"(regs[16]), "=r"(regs[17]), "=r"(regs[18]), "=r"(regs[19]),               \
          "=r"(regs[20]), "=r"(regs[21]), "=r"(regs[22]), "=r"(regs[23]),               \
          "=r"(regs[24]), "=r"(regs[25]), "=r"(regs[26]), "=r"(regs[27]),               \
          "=r"(regs[28]), "=r"(regs[29]), "=r"(regs[30]), "=r"(regs[31])                \
        : "r"(addr))
#endif  // HAS_TC

// ------------------------- small kernels -------------------------
__global__ void k_init() {
    int idx = blockIdx.x * blockDim.x + threadIdx.x;
    const float NEGINF = __int_as_float(0xff800000);
    if (idx < NN) g_deg[idx] = 0;
    if (idx < NN * 128) g_agg1[idx] = NEGINF;
    if (idx < NN * 1024) g_agg2[idx] = NEGINF;
}

__global__ void k_hist(const int* __restrict__ ei) {
    int e = blockIdx.x * blockDim.x + threadIdx.x;
    if (e < NE) atomicAdd(&g_deg[ei[NE + e]], 1);
}

__global__ void k_scan() {
    __shared__ int part[1024];
    int t = threadIdx.x;
    int base = t * 10;
    int loc[10];
    int s = 0;
#pragma unroll
    for (int i = 0; i < 10; i++) {
        int idx = base + i;
        int v = (idx < NN) ? g_deg[idx] : 0;
        loc[i] = s; s += v;
    }
    part[t] = s;
    __syncthreads();
    for (int off = 1; off < 1024; off <<= 1) {
        int v = 0;
        if (t >= off) v = part[t - off];
        __syncthreads();
        if (t >= off) part[t] += v;
        __syncthreads();
    }
    int excl = (t == 0) ? 0 : part[t - 1];
#pragma unroll
    for (int i = 0; i < 10; i++) {
        int idx = base + i;
        if (idx < NN) g_cur[idx] = excl + loc[i];
    }
}

__global__ void k_scatter(const int* __restrict__ ei) {
    int e = blockIdx.x * blockDim.x + threadIdx.x;
    if (e < NE) {
        int d = ei[NE + e];
        int p = atomicAdd(&g_cur[d], 1);
        g_srcs[p] = ei[e];
        g_dsts[p] = d;
    }
}

// W[K,F] fp32 -> split Wt[F,2K] (hi | lo), smem-tiled for coalesced writes
__global__ void k_cvtT_split_t(const float* __restrict__ W, __half* __restrict__ Wt,
                               int K, int F) {
    __shared__ float tile[32][33];
    int kt = blockIdx.y * 32, ft = blockIdx.x * 32;
    int tx = threadIdx.x, ty = threadIdx.y;  // 32 x 8
#pragma unroll
    for (int i = 0; i < 32; i += 8)
        tile[ty + i][tx] = W[(size_t)(kt + ty + i) * F + ft + tx];
    __syncthreads();
#pragma unroll
    for (int i = 0; i < 32; i += 8) {
        int f = ft + ty + i, k = kt + tx;
        float v = tile[tx][ty + i];
        __half hi = __float2half(v);
        Wt[(size_t)f * 2 * K + k] = hi;
        Wt[(size_t)f * 2 * K + K + k] = __float2half(v - __half2float(hi));
    }
}

// W (row-major [K, ld], use cols [0,F)) -> SW64 tcgen05 tiles [y(F/256)][ch(K/32)][hi|lo]
__global__ void k_cvt_wsw(const float* __restrict__ W, __half* __restrict__ out,
                          int K, int F, int ld) {
    int idx = blockIdx.x * blockDim.x + threadIdx.x;
    if (idx >= K * F) return;
    int k = idx / F, f = idx % F;
    float v = W[(size_t)k * ld + f];
    __half hi = __float2half(v);
    __half lo = __float2half(v - __half2float(hi));
    int y = f >> 8, r = f & 255, ch = k >> 5, c = k & 31;
    uint32_t bo = (uint32_t)(r * 64 + c * 2);
    uint32_t sw = bo ^ ((bo >> 3) & 0x30);
    size_t base = ((size_t)y * (K / 32) + ch) * 16384;
    out[base + (sw >> 1)] = hi;
    out[base + 8192 + (sw >> 1)] = lo;
}

// conv1 node precompute (fp32): A1 = x·(Wx+Wp)+b ; B1 = x·Wp
__global__ void k_precomp1(const float* __restrict__ x, const float* __restrict__ w,
                           const float* __restrict__ b) {
    int idx = blockIdx.x * blockDim.x + threadIdx.x;
    if (idx >= NN * 64) return;
    int n = idx >> 6, f = idx & 63;
    float x0 = x[2 * n], x1 = x[2 * n + 1];
    float w0 = w[f], w1 = w[64 + f], w2 = w[128 + f], w3 = w[192 + f];
    g_A1f[idx] = x0 * (w0 + w2) + x1 * (w1 + w3) + b[f];
    g_B1f[idx] = x0 * w2 + x1 * w3;
}

// conv2 pos precompute: D2 = x·Wp (rows 512,513 of l2w1 [514,1024])
__global__ void k_precompD2(const float* __restrict__ x, const float* __restrict__ l2w1) {
    int idx = blockIdx.x * blockDim.x + threadIdx.x;
    if (idx >= NN * 1024) return;
    int n = idx >> 10, f = idx & 1023;
    g_D2f[idx] = x[2 * n] * l2w1[512 * 1024 + f] + x[2 * n + 1] * l2w1[513 * 1024 + f];
}

// edge activations: ACT[p] = split(leaky(C2[src[p]] - D2[dst[p]])) — one block per edge
__global__ void __launch_bounds__(256)
k_edge_act(const float* __restrict__ C, const float* __restrict__ D) {
    int p = blockIdx.x;
    int s = g_srcs[p], d = g_dsts[p];
    int t = threadIdx.x;
    const float4 cv = *(const float4*)(C + (size_t)s * 1024 + t * 4);
    const float4 dv = *(const float4*)(D + (size_t)d * 1024 + t * 4);
    float m0 = leaky1f(cv.x - dv.x), m1 = leaky1f(cv.y - dv.y);
    float m2 = leaky1f(cv.z - dv.z), m3 = leaky1f(cv.w - dv.w);
    __half h0 = __float2half(m0), h1 = __float2half(m1);
    __half h2 = __float2half(m2), h3 = __float2half(m3);
    __half* base = g_ACT + (size_t)p * 2048 + t * 4;
    *(__half2*)(base) = __halves2half2(h0, h1);
    *(__half2*)(base + 2) = __halves2half2(h2, h3);
    *(__half2*)(base + 1024) = __halves2half2(__float2half(m0 - __half2float(h0)),
                                              __float2half(m1 - __half2float(h1)));
    *(__half2*)(base + 1026) = __halves2half2(__float2half(m2 - __half2float(h2)),
                                              __float2half(m3 - __half2float(h3)));
}

// agg fp32 -> hi/lo pair buffer [NN, 2F]
__global__ void k_fin_hl(const float* __restrict__ agg, __half* __restrict__ out,
                         int logF, int total) {
    int idx = blockIdx.x * blockDim.x + threadIdx.x;
    if (idx >= total) return;
    int F = 1 << logF;
    int n = idx >> logF, f = idx & (F - 1);
    float v = agg[idx];
    if (v < -1e30f) v = 0.0f;
    __half hi = __float2half(v);
    out[(size_t)n * 2 * F + f] = hi;
    out[(size_t)n * 2 * F + F + f] = __float2half(v - __half2float(hi));
}

// two-stage deterministic BN stats
__global__ void k_stats_partial(const float* __restrict__ P, int F) {
    int c = blockIdx.x * 128 + threadIdx.x;
    int r0 = blockIdx.y * 128;
    int r1 = r0 + 128; if (r1 > NN) r1 = NN;
    float s = 0.f, q = 0.f;
    for (int r = r0; r < r1; r++) {
        float v = P[(size_t)r * F + c];
        s += v; q += v * v;
    }
    g_part[(size_t)blockIdx.y * F + c] = s;
    g_partq[(size_t)blockIdx.y * F + c] = q;
}

__global__ void k_stats_final(int F) {
    int c = blockIdx.x * 128 + threadIdx.x;
    if (c >= F) return;
    float s = 0.f, q = 0.f;
    for (int t = 0; t < MTILES; t++) {
        s += g_part[(size_t)t * F + c];
        q += g_partq[(size_t)t * F + c];
    }
    float mu = s / NN;
    float var = fmaxf(q / NN - mu * mu, 0.0f);
    g_mu[c] = mu;
    g_rs[c] = rsqrtf(var + 1e-5f);
}

// BN -> hi/lo pair buffer
__global__ void k_norm_hl(const float* __restrict__ P, const float* __restrict__ gamma,
                          const float* __restrict__ beta, __half* __restrict__ out,
                          int logF, int total) {
    int idx = blockIdx.x * blockDim.x + threadIdx.x;
    if (idx >= total) return;
    int F = 1 << logF;
    int n = idx >> logF, f = idx & (F - 1);
    float v = gamma[f] * (P[idx] - g_mu[f]) * g_rs[f] + beta[f];
    __half hi = __float2half(v);
    out[(size_t)n * 2 * F + f] = hi;
    out[(size_t)n * 2 * F + F + f] = __float2half(v - __half2float(hi));
}

__global__ void k_norm_float(const float* __restrict__ P, const float* __restrict__ gamma,
                             const float* __restrict__ beta, float* __restrict__ out,
                             int mask, int total) {
    int idx = blockIdx.x * blockDim.x + threadIdx.x;
    if (idx < total) {
        int f = idx & mask;
        out[idx] = gamma[f] * (P[idx] - g_mu[f]) * g_rs[f] + beta[f];
    }
}

// ------------------------- node GEMM (legacy, conv1 only) -------------------------
#define NSTG 61440
#define NSMEM (3 * NSTG + 128)

template <int KB, int MODE>
__global__ void __launch_bounds__(512, 1)
k_ngemm(const __half* __restrict__ A, const __half* __restrict__ Wt,
        const float* __restrict__ bias, __half* __restrict__ outH,
        float* __restrict__ outF, const float* __restrict__ extra, int M) {
    extern __shared__ char dsm_raw[];
    char* dsm0 = (char*)(((uintptr_t)dsm_raw + 127) & ~(uintptr_t)127);
    const uint32_t sb0 = smem_u32(dsm0);

    const int tid = threadIdx.x;
    const int wid = tid >> 5;
    const int lane = tid & 31;
    const int wm = wid & 1, wn = wid >> 1;
    const int tileM = blockIdx.x;
    const int colg0 = blockIdx.y * 256;
    const int F = gridDim.y * 256;
    constexpr int NCH = KB / 32;

    auto load_chunk = [&](int ch) {
        const int k0 = ch * 32;
        const uint32_t sb = sb0 + (ch % 3) * NSTG;
        int r = tid >> 2, s = tid & 3;
        int rg = tileM * 128 + r;
        if (rg >= M) rg = M - 1;
        const __half* asrc = A + (size_t)rg * 2 * KB + k0 + s * 8;
        cp16(sb + r * 80 + s * 16, asrc);
        cp16(sb + 10240 + r * 80 + s * 16, asrc + KB);
#pragma unroll
        for (int i = 0; i < 2; i++) {
            int idx = tid + i * 512;
            int wr = idx >> 2, ws_ = idx & 3;
            const __half* wsrc = Wt + (size_t)(colg0 + wr) * 2 * KB + k0 + ws_ * 8;
            cp16(sb + 20480 + wr * 80 + ws_ * 16, wsrc);
            cp16(sb + 40960 + wr * 80 + ws_ * 16, wsrc + KB);
        }
        cp_commit();
    };

    float c[4][4][4];
#pragma unroll
    for (int i = 0; i < 4; i++)
#pragma unroll
        for (int j = 0; j < 4; j++)
#pragma unroll
            for (int k = 0; k < 4; k++) c[i][j][k] = 0.0f;

    load_chunk(0);

#pragma unroll 1
    for (int ch = 0; ch < NCH; ch++) {
        if (ch + 1 < NCH) {
            load_chunk(ch + 1);
            cp_wait1();
        } else {
            cp_wait0();
        }
        __syncthreads();
        __half* Ah = (__half*)(dsm0 + (ch % 3) * NSTG);
        __half* Al = Ah + 5120;
        __half* Bh = Ah + 10240;
        __half* Bl = Ah + 20480;
        mma_chunk_abb(Ah, Bh, Bl, lane, wm, wn, c);
        mma_chunk(Al, Bh, lane, wm, wn, c);
    }

#pragma unroll
    for (int mf = 0; mf < 4; mf++) {
#pragma unroll
        for (int nf = 0; nf < 4; nf++) {
            int rl = wm * 64 + mf * 16 + (lane >> 2);
            int cl = wn * 32 + nf * 8 + (lane & 3) * 2;
            int cg = colg0 + cl;
            float b0 = bias[cg], b1 = bias[cg + 1];
#pragma unroll
            for (int h = 0; h < 2; h++) {
                int rg = tileM * 128 + rl + h * 8;
                if (rg >= M) continue;
                float v0 = c[mf][nf][2 * h + 0] + b0;
                float v1 = c[mf][nf][2 * h + 1] + b1;
                if (MODE == 0) {
                    v0 = leaky1f(v0); v1 = leaky1f(v1);
                    __half h0 = __float2half(v0), h1 = __float2half(v1);
                    *(__half2*)&outH[(size_t)rg * 2 * F + cg] = __halves2half2(h0, h1);
                    *(__half2*)&outH[(size_t)rg * 2 * F + F + cg] = __halves2half2(
                        __float2half(v0 - __half2float(h0)), __float2half(v1 - __half2float(h1)));
                } else if (MODE == 1) {
                    v0 = leaky1f(leaky1f(v0)); v1 = leaky1f(leaky1f(v1));
                    *(float2*)&outF[(size_t)rg * F + cg] = make_float2(v0, v1);
                } else {
                    float2 ex = *(const float2*)&extra[(size_t)rg * F + cg];
                    *(float2*)&outF[(size_t)rg * F + cg] = make_float2(v0 + ex.x, v1 + ex.y);
                }
            }
        }
    }
}

// ------------------------- legacy edge GEMM (conv1, small) -------------------------
template <int KB, int NWN>
__global__ void __launch_bounds__(NWN * 64, 1)
k_edge_gemm(const float* __restrict__ Crow, const float* __restrict__ Drow,
            const __half* __restrict__ Wt, const float* __restrict__ bias,
            float* __restrict__ agg) {
    constexpr int NT = NWN * 32;
    constexpr int T = NWN * 64;
    extern __shared__ __align__(16) char dsm[];
    __half* As_hi = (__half*)dsm;
    __half* As_lo = As_hi + 128 * 40;
    __half* Bs_hi = As_lo + 128 * 40;
    __half* Bs_lo = Bs_hi + NT * 40;
    float* Cs = (float*)dsm;
    __shared__ int s_src[128];
    __shared__ int s_dst[128];

    const int tid = threadIdx.x;
    const int lane = tid & 31;
    const int warp = tid >> 5;
    const int wm = warp & 1, wn = warp >> 1;
    const int e0 = blockIdx.x * 128;
    const int colg0 = blockIdx.y * NT;
    const int F = gridDim.y * NT;

    if (tid < 128) {
        s_src[tid] = g_srcs[e0 + tid];
        s_dst[tid] = g_dsts[e0 + tid];
    }
    __syncthreads();

    float c[4][4][4];
#pragma unroll
    for (int i = 0; i < 4; i++)
#pragma unroll
        for (int j = 0; j < 4; j++)
#pragma unroll
            for (int k = 0; k < 4; k++) c[i][j][k] = 0.0f;

    for (int k0 = 0; k0 < KB; k0 += 32) {
#pragma unroll
        for (int i = 0; i < 1024 / T; i++) {
            int idx = tid + i * T;
            int r = idx >> 3, s = idx & 7;
            const float4 cv = *(const float4*)(Crow + (size_t)s_src[r] * KB + k0 + s * 4);
            const float4 dv = *(const float4*)(Drow + (size_t)s_dst[r] * KB + k0 + s * 4);
            float m0 = leaky1f(cv.x - dv.x), m1 = leaky1f(cv.y - dv.y);
            float m2 = leaky1f(cv.z - dv.z), m3 = leaky1f(cv.w - dv.w);
            __half h0 = __float2half(m0), h1 = __float2half(m1);
            __half h2 = __float2half(m2), h3 = __float2half(m3);
            int off = r * 40 + s * 4;
            *(__half2*)&As_hi[off] = __halves2half2(h0, h1);
            *(__half2*)&As_hi[off + 2] = __halves2half2(h2, h3);
            *(__half2*)&As_lo[off] = __halves2half2(__float2half(m0 - __half2float(h0)),
                                                    __float2half(m1 - __half2float(h1)));
            *(__half2*)&As_lo[off + 2] = __halves2half2(__float2half(m2 - __half2float(h2)),
                                                        __float2half(m3 - __half2float(h3)));
        }
#pragma unroll
        for (int i = 0; i < NT * 4 / T; i++) {
            int idx = tid + i * T;
            int r = idx >> 2, s = idx & 3;
            const __half* wrow = Wt + (size_t)(colg0 + r) * 2 * KB + k0 + s * 8;
            *(int4*)&Bs_hi[r * 40 + s * 8] = *(const int4*)wrow;
            *(int4*)&Bs_lo[r * 40 + s * 8] = *(const int4*)(wrow + KB);
        }
        __syncthreads();
        mma_chunk_abb(As_hi, Bs_hi, Bs_lo, lane, wm, wn, c);
        mma_chunk(As_lo, Bs_hi, lane, wm, wn, c);
        __syncthreads();
    }

#pragma unroll
    for (int mf = 0; mf < 4; mf++) {
#pragma unroll
        for (int nf = 0; nf < 4; nf++) {
            int rl = wm * 64 + mf * 16 + (lane >> 2);
            int cl = wn * 32 + nf * 8 + (lane & 3) * 2;
            float b0 = bias[colg0 + cl], b1 = bias[colg0 + cl + 1];
#pragma unroll
            for (int h = 0; h < 2; h++) {
                float v0 = leaky1f(c[mf][nf][2 * h + 0] + b0);
                float v1 = leaky1f(c[mf][nf][2 * h + 1] + b1);
                *(float2*)&Cs[(rl + h * 8) * (NT + 2) + cl] = make_float2(v0, v1);
            }
        }
    }
    __syncthreads();

    {
        int col = tid & (NT - 1);
        int rbeg = (tid >= NT) ? 64 : 0;
        float cur = __int_as_float(0xff800000);
        int curd = s_dst[rbeg];
        for (int r = rbeg; r < rbeg + 64; r++) {
            int d = s_dst[r];
            if (d != curd) {
                atomicMaxF(&agg[(size_t)curd * F + colg0 + col], cur);
                cur = __int_as_float(0xff800000);
                curd = d;
            }
            cur = fmaxf(cur, Cs[r * (NT + 2) + col]);
        }
        atomicMaxF(&agg[(size_t)curd * F + colg0 + col], cur);
    }
}

// ------------------------- shared tile sizes -------------------------
#define EK_SLOT 65536
#define EK_SMEM (3 * EK_SLOT + 1024)
#define LSTG    61440

// ------------------------- conv2 edge GEMM: tcgen05, M=256 shared-W (round-13 proven) ----------
__global__ void __launch_bounds__(512, 1)
k_edge_tc(const float* __restrict__ bias, float* __restrict__ agg) {
    extern __shared__ char dsm_raw[];
    char* dsm0 = (char*)(((uintptr_t)dsm_raw + 1023) & ~(uintptr_t)1023);
    __shared__ int s_dst[256];

    const int tid = threadIdx.x;
    const int wid = tid >> 5;
    const int lane = tid & 31;
    const int e0 = blockIdx.x * 256;
    const int y = blockIdx.y;
    const int colg0 = y * 256;

    if (tid < 256) s_dst[tid] = g_dsts[e0 + tid];

    float* Cs = (float*)dsm0;  // 128 x 258 fp32 per tile pass

#if HAS_TC
    __shared__ __align__(8) uint64_t s_mbar[3];
    __shared__ uint32_t s_tmem;
    const uint32_t sbase = smem_u32(dsm0);

    if (tid == 0) {
        mbar_init(smem_u32(&s_mbar[0]), 1);
        mbar_init(smem_u32(&s_mbar[1]), 1);
        mbar_init(smem_u32(&s_mbar[2]), 1);
    }
    if (wid == 0) {
        asm volatile("tcgen05.alloc.cta_group::1.sync.aligned.shared::cta.b32 [%0], %1;"
                     :: "r"(smem_u32(&s_tmem)), "r"(512u) : "memory");
    }
    __syncthreads();
    const uint32_t tmem = s_tmem;

    const uint32_t IDESC = (1u << 4) | (32u << 17) | (8u << 24);
    int wp[3] = {0, 0, 0};

    auto load_chunk = [&](int ch) {
        const uint32_t su = sbase + (ch % 3) * EK_SLOT;
        const int k0h = ch * 32;
        int r = tid >> 2, s = tid & 3;
        uint32_t bo = (uint32_t)(r * 64 + s * 16);
        uint32_t sw = bo ^ ((bo >> 3) & 0x30);
#pragma unroll
        for (int t = 0; t < 2; t++) {
            const __half* src = g_ACT + (size_t)(e0 + t * 128 + r) * 2048 + k0h + s * 8;
            cp16(su + t * 16384 + sw, src);
            cp16(su + t * 16384 + 8192 + sw, src + 1024);
        }
        const char* ws = (const char*)(g_W2sw + ((size_t)y * 32 + ch) * 16384);
#pragma unroll
        for (int i = 0; i < 4; i++) {
            int j = tid + i * 512;
            cp16(su + 32768 + j * 16, ws + j * 16);
        }
        cp_commit();
    };

    load_chunk(0);

#pragma unroll 1
    for (int ch = 0; ch < 32; ch++) {
        if (ch + 1 < 32) {
            int c = ch + 1, sl = c % 3;
            if (c >= 3) { mbar_wait(smem_u32(&s_mbar[sl]), wp[sl] & 1); wp[sl]++; }
            load_chunk(c);
            cp_wait1();
        } else {
            cp_wait0();
        }
        asm volatile("fence.proxy.async.shared::cta;" ::: "memory");
        __syncthreads();
        if (wid == 0 && elect_one_pred()) {
            const uint32_t su = sbase + (ch % 3) * EK_SLOT;
            uint64_t a0h = make_desc64(su);
            uint64_t a0l = make_desc64(su + 8192);
            uint64_t a1h = make_desc64(su + 16384);
            uint64_t a1l = make_desc64(su + 24576);
            uint64_t wh  = make_desc64(su + 32768);
            uint64_t wl  = make_desc64(su + 49152);
#pragma unroll
            for (int ks = 0; ks < 2; ks++) {
                uint32_t en = (ch == 0 && ks == 0) ? 0u : 1u;
                mma_f16_ss_cg1(tmem,       a0h + ks * 2, wh + ks * 2, IDESC, en);
                mma_f16_ss_cg1(tmem,       a0l + ks * 2, wh + ks * 2, IDESC, 1u);
                mma_f16_ss_cg1(tmem,       a0h + ks * 2, wl + ks * 2, IDESC, 1u);
                mma_f16_ss_cg1(tmem + 256, a1h + ks * 2, wh + ks * 2, IDESC, en);
                mma_f16_ss_cg1(tmem + 256, a1l + ks * 2, wh + ks * 2, IDESC, 1u);
                mma_f16_ss_cg1(tmem + 256, a1h + ks * 2, wl + ks * 2, IDESC, 1u);
            }
            asm volatile(
                "tcgen05.commit.cta_group::1.mbarrier::arrive::one.shared::cluster.b64 [%0];"
                :: "r"(smem_u32(&s_mbar[ch % 3])) : "memory");
        }
    }
    mbar_wait(smem_u32(&s_mbar[0]), wp[0] & 1);
    mbar_wait(smem_u32(&s_mbar[1]), wp[1] & 1);
    mbar_wait(smem_u32(&s_mbar[2]), wp[2] & 1);
    asm volatile("tcgen05.fence::after_thread_sync;" ::: "memory");
    __syncthreads();

#pragma unroll 1
    for (int t = 0; t < 2; t++) {
        if (wid < 4) {
            int row = wid * 32 + lane;
#pragma unroll 1
            for (int cc = 0; cc < 8; cc++) {
                uint32_t regs[32];
                LDTM32(regs, tmem + t * 256 + cc * 32);
                asm volatile("tcgen05.wait::ld.sync.aligned;" ::: "memory");
#pragma unroll
                for (int j = 0; j < 32; j++) {
                    int col = cc * 32 + j;
                    Cs[row * 258 + col] = leaky1f(__uint_as_float(regs[j]) + bias[colg0 + col]);
                }
            }
            asm volatile("tcgen05.fence::before_thread_sync;" ::: "memory");
        }
        __syncthreads();
        {
            int col = tid & 255;
            int rbeg = (tid >= 256) ? 64 : 0;
            float cur = __int_as_float(0xff800000);
            int curd = s_dst[t * 128 + rbeg];
#pragma unroll 1
            for (int r = rbeg; r < rbeg + 64; r++) {
                int d = s_dst[t * 128 + r];
                if (d != curd) {
                    atomicMaxF(&agg[(size_t)curd * 1024 + colg0 + col], cur);
                    cur = __int_as_float(0xff800000);
                    curd = d;
                }
                cur = fmaxf(cur, Cs[r * 258 + col]);
            }
            atomicMaxF(&agg[(size_t)curd * 1024 + colg0 + col], cur);
        }
        __syncthreads();
    }

    if (wid == 0) {
        asm volatile("tcgen05.relinquish_alloc_permit.cta_group::1.sync.aligned;");
        asm volatile("tcgen05.dealloc.cta_group::1.sync.aligned.b32 %0, %1;"
                     :: "r"(tmem), "r"(512u));
    }
#else
    // legacy fallback: two 128-edge tiles sequentially
    const int wm = wid & 1, wn = wid >> 1;
    const uint32_t sb0 = smem_u32(dsm0);

#pragma unroll 1
    for (int t = 0; t < 2; t++) {
        __syncthreads();
        float c[4][4][4];
#pragma unroll
        for (int i = 0; i < 4; i++)
#pragma unroll
            for (int j = 0; j < 4; j++)
#pragma unroll
                for (int k = 0; k < 4; k++) c[i][j][k] = 0.0f;

        auto load_chunk = [&](int ch) {
            const int k0 = ch * 32;
            const uint32_t sb = sb0 + (ch % 3) * LSTG;
            int r = tid >> 2, s = tid & 3;
            const __half* asrc = g_ACT + (size_t)(e0 + t * 128 + r) * 2048 + k0 + s * 8;
            cp16(sb + r * 80 + s * 16, asrc);
            cp16(sb + 10240 + r * 80 + s * 16, asrc + 1024);
#pragma unroll
            for (int i = 0; i < 2; i++) {
                int idx = tid + i * 512;
                int wr = idx >> 2, ws_ = idx & 3;
                const __half* wsrc = g_W_l2w2 + (size_t)(colg0 + wr) * 2048 + k0 + ws_ * 8;
                cp16(sb + 20480 + wr * 80 + ws_ * 16, wsrc);
                cp16(sb + 40960 + wr * 80 + ws_ * 16, wsrc + 1024);
            }
            cp_commit();
        };

        load_chunk(0);
#pragma unroll 1
        for (int ch = 0; ch < 32; ch++) {
            if (ch + 1 < 32) { load_chunk(ch + 1); cp_wait1(); }
            else             { cp_wait0(); }
            __syncthreads();
            __half* Ah = (__half*)(dsm0 + (ch % 3) * LSTG);
            __half* Al = Ah + 5120;
            __half* Bh = Ah + 10240;
            __half* Bl = Ah + 20480;
            mma_chunk_abb(Ah, Bh, Bl, lane, wm, wn, c);
            mma_chunk(Al, Bh, lane, wm, wn, c);
        }
        __syncthreads();

#pragma unroll
        for (int mf = 0; mf < 4; mf++) {
#pragma unroll
            for (int nf = 0; nf < 4; nf++) {
                int rl = wm * 64 + mf * 16 + (lane >> 2);
                int cl = wn * 32 + nf * 8 + (lane & 3) * 2;
                float b0 = bias[colg0 + cl], b1 = bias[colg0 + cl + 1];
#pragma unroll
                for (int h = 0; h < 2; h++) {
                    float v0 = leaky1f(c[mf][nf][2 * h + 0] + b0);
                    float v1 = leaky1f(c[mf][nf][2 * h + 1] + b1);
                    *(float2*)&Cs[(rl + h * 8) * 258 + cl] = make_float2(v0, v1);
                }
            }
        }
        __syncthreads();
        {
            int col = tid & 255;
            int rbeg = (tid >= 256) ? 64 : 0;
            float cur = __int_as_float(0xff800000);
            int curd = s_dst[t * 128 + rbeg];
#pragma unroll 1
            for (int r = rbeg; r < rbeg + 64; r++) {
                int d = s_dst[t * 128 + r];
                if (d != curd) {
                    atomicMaxF(&agg[(size_t)curd * 1024 + colg0 + col], cur);
                    cur = __int_as_float(0xff800000);
                    curd = d;
                }
                cur = fmaxf(cur, Cs[r * 258 + col]);
            }
            atomicMaxF(&agg[(size_t)curd * 1024 + colg0 + col], cur);
        }
        __syncthreads();
    }
#endif
}

// ------------------------- dense node GEMM: tcgen05, 256 rows x 256 cols -------------------------
// Same machinery as k_edge_tc but dense A rows and MODE-specific coalesced epilogue.
template <int KB, int MODE>
__global__ void __launch_bounds__(512, 1)
k_ngemm_tc(const __half* __restrict__ A, const __half* __restrict__ Wsw,
           const __half* __restrict__ Wleg, const float* __restrict__ bias,
           __half* __restrict__ outH, float* __restrict__ outF,
           const float* __restrict__ extra, int M) {
    extern __shared__ char dsm_raw[];
    char* dsm0 = (char*)(((uintptr_t)dsm_raw + 1023) & ~(uintptr_t)1023);

    const int tid = threadIdx.x;
    const int wid = tid >> 5;
    const int lane = tid & 31;
    const int tileM = blockIdx.x;   // 256-row tiles
    const int y = blockIdx.y;
    const int colg0 = y * 256;
    const int F = gridDim.y * 256;
    constexpr int NCH = KB / 32;

    float* Cs = (float*)dsm0;  // 128 x 258

#if HAS_TC
    __shared__ __align__(8) uint64_t s_mbar[3];
    __shared__ uint32_t s_tmem;
    const uint32_t sbase = smem_u32(dsm0);

    if (tid == 0) {
        mbar_init(smem_u32(&s_mbar[0]), 1);
        mbar_init(smem_u32(&s_mbar[1]), 1);
        mbar_init(smem_u32(&s_mbar[2]), 1);
    }
    if (wid == 0) {
        asm volatile("tcgen05.alloc.cta_group::1.sync.aligned.shared::cta.b32 [%0], %1;"
                     :: "r"(smem_u32(&s_tmem)), "r"(512u) : "memory");
    }
    __syncthreads();
    const uint32_t tmem = s_tmem;

    const uint32_t IDESC = (1u << 4) | (32u << 17) | (8u << 24);
    int wp[3] = {0, 0, 0};

    auto load_chunk = [&](int ch) {
        const uint32_t su = sbase + (ch % 3) * EK_SLOT;
        const int k0h = ch * 32;
        int r = tid >> 2, s = tid & 3;
        uint32_t bo = (uint32_t)(r * 64 + s * 16);
        uint32_t sw = bo ^ ((bo >> 3) & 0x30);
#pragma unroll
        for (int t = 0; t < 2; t++) {
            int rg = tileM * 256 + t * 128 + r;
            if (rg >= M) rg = M - 1;
            const __half* src = A + (size_t)rg * 2 * KB + k0h + s * 8;
            cp16(su + t * 16384 + sw, src);
            cp16(su + t * 16384 + 8192 + sw, src + KB);
        }
        const char* ws = (const char*)(Wsw + ((size_t)y * NCH + ch) * 16384);
#pragma unroll
        for (int i = 0; i < 4; i++) {
            int j = tid + i * 512;
            cp16(su + 32768 + j * 16, ws + j * 16);
        }
        cp_commit();
    };

    load_chunk(0);

#pragma unroll 1
    for (int ch = 0; ch < NCH; ch++) {
        if (ch + 1 < NCH) {
            int c = ch + 1, sl = c % 3;
            if (c >= 3) { mbar_wait(smem_u32(&s_mbar[sl]), wp[sl] & 1); wp[sl]++; }
            load_chunk(c);
            cp_wait1();
        } else {
            cp_wait0();
        }
        asm volatile("fence.proxy.async.shared::cta;" ::: "memory");
        __syncthreads();
        if (wid == 0 && elect_one_pred()) {
            const uint32_t su = sbase + (ch % 3) * EK_SLOT;
            uint64_t a0h = make_desc64(su);
            uint64_t a0l = make_desc64(su + 8192);
            uint64_t a1h = make_desc64(su + 16384);
            uint64_t a1l = make_desc64(su + 24576);
            uint64_t wh  = make_desc64(su + 32768);
            uint64_t wl  = make_desc64(su + 49152);
#pragma unroll
            for (int ks = 0; ks < 2; ks++) {
                uint32_t en = (ch == 0 && ks == 0) ? 0u : 1u;
                mma_f16_ss_cg1(tmem,       a0h + ks * 2, wh + ks * 2, IDESC, en);
                mma_f16_ss_cg1(tmem,       a0l + ks * 2, wh + ks * 2, IDESC, 1u);
                mma_f16_ss_cg1(tmem,       a0h + ks * 2, wl + ks * 2, IDESC, 1u);
                mma_f16_ss_cg1(tmem + 256, a1h + ks * 2, wh + ks * 2, IDESC, en);
                mma_f16_ss_cg1(tmem + 256, a1l + ks * 2, wh + ks * 2, IDESC, 1u);
                mma_f16_ss_cg1(tmem + 256, a1h + ks * 2, wl + ks * 2, IDESC, 1u);
            }
            asm volatile(
                "tcgen05.commit.cta_group::1.mbarrier::arrive::one.shared::cluster.b64 [%0];"
                :: "r"(smem_u32(&s_mbar[ch % 3])) : "memory");
        }
    }
    mbar_wait(smem_u32(&s_mbar[0]), wp[0] & 1);
    mbar_wait(smem_u32(&s_mbar[1]), wp[1] & 1);
    mbar_wait(smem_u32(&s_mbar[2]), wp[2] & 1);
    asm volatile("tcgen05.fence::after_thread_sync;" ::: "memory");
    __syncthreads();

#pragma unroll 1
    for (int t = 0; t < 2; t++) {
        if (wid < 4) {
            int row = wid * 32 + lane;
#pragma unroll 1
            for (int cc = 0; cc < 8; cc++) {
                uint32_t regs[32];
                LDTM32(regs, tmem + t * 256 + cc * 32);
                asm volatile("tcgen05.wait::ld.sync.aligned;" ::: "memory");
#pragma unroll
                for (int j = 0; j < 32; j++) {
                    int col = cc * 32 + j;
                    Cs[row * 258 + col] = __uint_as_float(regs[j]) + bias[colg0 + col];
                }
            }
            asm volatile("tcgen05.fence::before_thread_sync;" ::: "memory");
        }
        __syncthreads();
        // coalesced MODE-specific writes
#pragma unroll 1
        for (int i = tid; i < 128 * 256; i += 512) {
            int r = i >> 8, col = i & 255;
            int rg = tileM * 256 + t * 128 + r;
            if (rg < M) {
                float v = Cs[r * 258 + col];
                int cg = colg0 + col;
                if (MODE == 0) {
                    v = leaky1f(v);
                    __half hi = __float2half(v);
                    outH[(size_t)rg * 2 * F + cg] = hi;
                    outH[(size_t)rg * 2 * F + F + cg] = __float2half(v - __half2float(hi));
                } else if (MODE == 1) {
                    outF[(size_t)rg * F + cg] = leaky1f(leaky1f(v));
                } else {
                    outF[(size_t)rg * F + cg] = v + extra[(size_t)rg * F + cg];
                }
            }
        }
        __syncthreads();
    }

    if (wid == 0) {
        asm volatile("tcgen05.relinquish_alloc_permit.cta_group::1.sync.aligned;");
        asm volatile("tcgen05.dealloc.cta_group::1.sync.aligned.b32 %0, %1;"
                     :: "r"(tmem), "r"(512u));
    }
#else
    // legacy fallback: two 128-row tiles sequentially (k_ngemm structure)
    const int wm = wid & 1, wn = wid >> 1;
    const uint32_t sb0 = smem_u32(dsm0);

#pragma unroll 1
    for (int t = 0; t < 2; t++) {
        __syncthreads();
        float c[4][4][4];
#pragma unroll
        for (int i = 0; i < 4; i++)
#pragma unroll
            for (int j = 0; j < 4; j++)
#pragma unroll
                for (int k = 0; k < 4; k++) c[i][j][k] = 0.0f;

        auto load_chunk = [&](int ch) {
            const int k0 = ch * 32;
            const uint32_t sb = sb0 + (ch % 3) * LSTG;
            int r = tid >> 2, s = tid & 3;
            int rg = tileM * 256 + t * 128 + r;
            if (rg >= M) rg = M - 1;
            const __half* asrc = A + (size_t)rg * 2 * KB + k0 + s * 8;
            cp16(sb + r * 80 + s * 16, asrc);
            cp16(sb + 10240 + r * 80 + s * 16, asrc + KB);
#pragma unroll
            for (int i = 0; i < 2; i++) {
                int idx = tid + i * 512;
                int wr = idx >> 2, ws_ = idx & 3;
                const __half* wsrc = Wleg + (size_t)(colg0 + wr) * 2 * KB + k0 + ws_ * 8;
                cp16(sb + 20480 + wr * 80 + ws_ * 16, wsrc);
                cp16(sb + 40960 + wr * 80 + ws_ * 16, wsrc + KB);
            }
            cp_commit();
        };

        load_chunk(0);
#pragma unroll 1
        for (int ch = 0; ch < NCH; ch++) {
            if (ch + 1 < NCH) { load_chunk(ch + 1); cp_wait1(); }
            else              { cp_wait0(); }
            __syncthreads();
            __half* Ah = (__half*)(dsm0 + (ch % 3) * LSTG);
            __half* Al = Ah + 5120;
            __half* Bh = Ah + 10240;
            __half* Bl = Ah + 20480;
            mma_chunk_abb(Ah, Bh, Bl, lane, wm, wn, c);
            mma_chunk(Al, Bh, lane, wm, wn, c);
        }
        __syncthreads();

#pragma unroll
        for (int mf = 0; mf < 4; mf++) {
#pragma unroll
            for (int nf = 0; nf < 4; nf++) {
                int rl = wm * 64 + mf * 16 + (lane >> 2);
                int cl = wn * 32 + nf * 8 + (lane & 3) * 2;
                int cg = colg0 + cl;
                float b0 = bias[cg], b1 = bias[cg + 1];
#pragma unroll
                for (int h = 0; h < 2; h++) {
                    int rg = tileM * 256 + t * 128 + rl + h * 8;
                    if (rg >= M) continue;
                    float v0 = c[mf][nf][2 * h + 0] + b0;
                    float v1 = c[mf][nf][2 * h + 1] + b1;
                    if (MODE == 0) {
                        v0 = leaky1f(v0); v1 = leaky1f(v1);
                        __half h0 = __float2half(v0), h1 = __float2half(v1);
                        *(__half2*)&outH[(size_t)rg * 2 * F + cg] = __halves2half2(h0, h1);
                        *(__half2*)&outH[(size_t)rg * 2 * F + F + cg] = __halves2half2(
                            __float2half(v0 - __half2float(h0)),
                            __float2half(v1 - __half2float(h1)));
                    } else if (MODE == 1) {
                        v0 = leaky1f(leaky1f(v0)); v1 = leaky1f(leaky1f(v1));
                        *(float2*)&outF[(size_t)rg * F + cg] = make_float2(v0, v1);
                    } else {
                        float2 ex = *(const float2*)&extra[(size_t)rg * F + cg];
                        *(float2*)&outF[(size_t)rg * F + cg] = make_float2(v0 + ex.x, v1 + ex.y);
                    }
                }
            }
        }
        __syncthreads();
    }
#endif
}

// ------------------------- host -------------------------
static void* sym(const void* s) {
    void* p = nullptr;
    cudaGetSymbolAddress(&p, s);
    return p;
}

extern "C" void kernel_launch(void* const* d_in, const int* in_sizes, int n_in,
                              void* d_out, int out_size) {
    const float* x    = (const float*)d_in[0];
    const int*   ei   = (const int*)d_in[1];
    const float* l1w1 = (const float*)d_in[3];
    const float* l1b1 = (const float*)d_in[4];
    const float* l1w2 = (const float*)d_in[5];
    const float* l1b2 = (const float*)d_in[6];
    const float* g1w1 = (const float*)d_in[7];
    const float* g1b1 = (const float*)d_in[8];
    const float* g1w2 = (const float*)d_in[9];
    const float* g1b2 = (const float*)d_in[10];
    const float* gamma1 = (const float*)d_in[11];
    const float* beta1  = (const float*)d_in[12];
    const float* l2w1 = (const float*)d_in[13];
    const float* l2b1 = (const float*)d_in[14];
    const float* l2w2 = (const float*)d_in[15];
    const float* l2b2 = (const float*)d_in[16];
    const float* g2w1 = (const float*)d_in[17];
    const float* g2b1 = (const float*)d_in[18];
    const float* g2w2 = (const float*)d_in[19];
    const float* g2b2 = (const float*)d_in[20];
    const float* gamma2 = (const float*)d_in[21];
    const float* beta2  = (const float*)d_in[22];

    float*  A1f    = (float*)sym(g_A1f);
    float*  B1f    = (float*)sym(g_B1f);
    float*  agg1   = (float*)sym(g_agg1);
    __half* agg1hl = (__half*)sym(g_agg1hl);
    __half* T1hl   = (__half*)sym(g_T1hl);
    float*  P1     = (float*)sym(g_P1);
    __half* H1hl   = (__half*)sym(g_H1hl);
    float*  C2f    = (float*)sym(g_C2f);
    float*  D2f    = (float*)sym(g_D2f);
    float*  agg2   = (float*)sym(g_agg2);
    __half* agg2hl = (__half*)sym(g_agg2hl);
    __half* U2hl   = (__half*)sym(g_U2hl);
    float*  P2     = (float*)sym(g_P2);
    __half* W_l1w2 = (__half*)sym(g_W_l1w2);
    __half* W_g1w1 = (__half*)sym(g_W_g1w1);
    __half* W_g1w2 = (__half*)sym(g_W_g1w2);
    __half* W_l2w1 = (__half*)sym(g_W_l2w1);
    __half* W_g2w1 = (__half*)sym(g_W_g2w1);
    __half* W_g2w2 = (__half*)sym(g_W_g2w2);
    __half* Wsw_l2w1 = (__half*)sym(g_Wsw_l2w1);
    __half* Wsw_g2w1 = (__half*)sym(g_Wsw_g2w1);
    __half* Wsw_g2w2 = (__half*)sym(g_Wsw_g2w2);
    __half* W2sw     = (__half*)sym(g_W2sw);

    cudaFuncSetAttribute(k_edge_gemm<64, 4>, cudaFuncAttributeMaxDynamicSharedMemorySize,
                         128 * 130 * 4);
    cudaFuncSetAttribute(k_edge_tc, cudaFuncAttributeMaxDynamicSharedMemorySize, EK_SMEM);
    cudaFuncSetAttribute(k_ngemm<128, 0>, cudaFuncAttributeMaxDynamicSharedMemorySize, NSMEM);
    cudaFuncSetAttribute(k_ngemm<256, 1>, cudaFuncAttributeMaxDynamicSharedMemorySize, NSMEM);
    cudaFuncSetAttribute(k_ngemm_tc<512, 2>, cudaFuncAttributeMaxDynamicSharedMemorySize, EK_SMEM);
    cudaFuncSetAttribute(k_ngemm_tc<1024, 0>, cudaFuncAttributeMaxDynamicSharedMemorySize, EK_SMEM);
    cudaFuncSetAttribute(k_ngemm_tc<2048, 1>, cudaFuncAttributeMaxDynamicSharedMemorySize, EK_SMEM);

    // CSR build
    k_init<<<(NN * 1024 + 255) / 256, 256>>>();
    k_hist<<<(NE + 255) / 256, 256>>>(ei);
    k_scan<<<1, 1024>>>();
    k_scatter<<<(NE + 255) / 256, 256>>>(ei);

    // weights -> legacy split (conv1 + fallbacks) and SW64 tcgen05 tiles
    dim3 tb(32, 8);
    k_cvtT_split_t<<<dim3(128 / 32, 64 / 32), tb>>>(l1w2, W_l1w2, 64, 128);
    k_cvtT_split_t<<<dim3(256 / 32, 128 / 32), tb>>>(g1w1, W_g1w1, 128, 256);
    k_cvtT_split_t<<<dim3(512 / 32, 256 / 32), tb>>>(g1w2, W_g1w2, 256, 512);
    k_cvtT_split_t<<<dim3(1024 / 32, 512 / 32), tb>>>(l2w1, W_l2w1, 512, 1024);
    k_cvtT_split_t<<<dim3(1024 / 32, 1024 / 32), tb>>>(l2w2, (__half*)sym(g_W_l2w2), 1024, 1024);
    k_cvtT_split_t<<<dim3(2048 / 32, 1024 / 32), tb>>>(g2w1, W_g2w1, 1024, 2048);
    k_cvtT_split_t<<<dim3(2048 / 32, 2048 / 32), tb>>>(g2w2, W_g2w2, 2048, 2048);
    k_cvt_wsw<<<(1024 * 1024 + 255) / 256, 256>>>(l2w2, W2sw, 1024, 1024, 1024);
    k_cvt_wsw<<<(512 * 1024 + 255) / 256, 256>>>(l2w1, Wsw_l2w1, 512, 1024, 1024);
    k_cvt_wsw<<<(1024 * 2048 + 255) / 256, 256>>>(g2w1, Wsw_g2w1, 1024, 2048, 2048);
    k_cvt_wsw<<<(2048 * 2048 + 255) / 256, 256>>>(g2w2, Wsw_g2w2, 2048, 2048, 2048);

    // conv1
    k_precomp1<<<(NN * 64 + 255) / 256, 256>>>(x, l1w1, l1b1);
    k_edge_gemm<64, 4><<<dim3(NE / 128, 1), 256, 128 * 130 * 4>>>(A1f, B1f, W_l1w2, l1b2, agg1);
    k_fin_hl<<<(NN * 128 + 255) / 256, 256>>>(agg1, agg1hl, 7, NN * 128);
    k_ngemm<128, 0><<<dim3(MTILES, 1), 512, NSMEM>>>(agg1hl, W_g1w1, g1b1, T1hl, nullptr, nullptr, NN);
    k_ngemm<256, 1><<<dim3(MTILES, 2), 512, NSMEM>>>(T1hl, W_g1w2, g1b2, nullptr, P1, nullptr, NN);
    k_stats_partial<<<dim3(4, MTILES), 128>>>(P1, 512);
    k_stats_final<<<4, 128>>>(512);
    k_norm_hl<<<(NN * 512 + 255) / 256, 256>>>(P1, gamma1, beta1, H1hl, 9, NN * 512);

    // conv2
    k_precompD2<<<(NN * 1024 + 255) / 256, 256>>>(x, l2w1);
    k_ngemm_tc<512, 2><<<dim3(40, 4), 512, EK_SMEM>>>(H1hl, Wsw_l2w1, W_l2w1, l2b1,
                                                      nullptr, C2f, D2f, NN);
    k_edge_act<<<NE, 256>>>(C2f, D2f);
    k_edge_tc<<<dim3(NE / 256, 4), 512, EK_SMEM>>>(l2b2, agg2);
    k_fin_hl<<<(NN * 1024 + 255) / 256, 256>>>(agg2, agg2hl, 10, NN * 1024);
    k_ngemm_tc<1024, 0><<<dim3(40, 8), 512, EK_SMEM>>>(agg2hl, Wsw_g2w1, W_g2w1, g2b1,
                                                       U2hl, nullptr, nullptr, NN);
    k_ngemm_tc<2048, 1><<<dim3(40, 8), 512, EK_SMEM>>>(U2hl, Wsw_g2w2, W_g2w2, g2b2,
                                                       nullptr, P2, nullptr, NN);
    k_stats_partial<<<dim3(16, MTILES), 128>>>(P2, 2048);
    k_stats_final<<<16, 128>>>(2048);
    k_norm_float<<<(NN * 2048 + 255) / 256, 256>>>(P2, gamma2, beta2, (float*)d_out, 2047,
                                                   NN * 2048);
}

// round 17
// speedup vs baseline: 1.4508x; 1.0694x over previous
#include <cuda_runtime.h>
#include <cuda_fp16.h>
#include <stdint.h>

#define NN 10000
#define NE 160000
#define MTILES 79  // ceil(10000/128)

#if defined(__CUDA_ARCH_FEAT_SM103_ALL) || defined(__CUDA_ARCH_FEAT_SM100_ALL)
#define HAS_TC 1
#else
#define HAS_TC 0
#endif

// ------------------------- device scratch -------------------------
__device__ int g_deg[NN];
__device__ int g_cur[NN];
__device__ int g_srcs[NE];
__device__ int g_dsts[NE];

__device__ float  g_A1f[NN * 64];
__device__ float  g_B1f[NN * 64];
__device__ float  g_agg1[NN * 128];
__device__ __half g_agg1hl[NN * 256];
__device__ __half g_T1hl[NN * 512];
__device__ float  g_P1[NN * 512];
__device__ __half g_H1hl[NN * 1024];
__device__ float  g_C2f[NN * 1024];
__device__ float  g_D2f[NN * 1024];
__device__ float  g_agg2[NN * 1024];
__device__ __half g_agg2hl[NN * 2048];
__device__ __half g_U2hl[NN * 4096];
__device__ float  g_P2[NN * 2048];
__device__ float  g_mu[2048];
__device__ float  g_rs[2048];
__device__ float  g_part[MTILES * 2048];
__device__ float  g_partq[MTILES * 2048];

// edge activations (CSR order): [p][0,1024)=hi, [1024,2048)=lo
__device__ __half g_ACT[(size_t)NE * 2048];

// split weights, layout [F, 2K]: [0,K)=hi, [K,2K)=lo (legacy kernels + fallbacks)
__device__ __half g_W_l1w2[128 * 128];
__device__ __half g_W_g1w1[256 * 256];
__device__ __half g_W_g1w2[512 * 512];
__device__ __half g_W_l2w1[1024 * 1024];
__device__ __half g_W_l2w2[1024 * 2048];
__device__ __half g_W_g2w1[2048 * 2048];
__device__ __half g_W_g2w2[2048 * 4096];

// SW64-swizzled tcgen05 weight tiles: [y(F/256)][ch(K/32)][hi 8192 | lo 8192] halves,
// tile = 256 rows x 32 halves (64B rows).
__device__ __half g_W2sw[4 * 32 * 16384];       // l2w2  K=1024 F=1024
__device__ __half g_Wsw_l2w1[4 * 16 * 16384];   // l2w1  K=512  F=1024
__device__ __half g_Wsw_g2w1[8 * 32 * 16384];   // g2w1  K=1024 F=2048
__device__ __half g_Wsw_g2w2[8 * 64 * 16384];   // g2w2  K=2048 F=2048
__device__ __half g_Wsw_g1w1[1 * 4 * 16384];    // g1w1  K=128  F=256
__device__ __half g_Wsw_g1w2[2 * 8 * 16384];    // g1w2  K=256  F=512

// ------------------------- helpers -------------------------
__device__ __forceinline__ float leaky1f(float v) { return v > 0.0f ? v : 0.05f * v; }

__device__ __forceinline__ void atomicMaxF(float* addr, float v) {
    if (v >= 0.0f) atomicMax((int*)addr, __float_as_int(v));
    else           atomicMin((unsigned int*)addr, (unsigned int)__float_as_int(v));
}

__device__ __forceinline__ uint32_t smem_u32(const void* p) {
    return (uint32_t)__cvta_generic_to_shared(p);
}

__device__ __forceinline__ void cp16(uint32_t dst, const void* src) {
    asm volatile("cp.async.cg.shared.global [%0], [%1], 16;" :: "r"(dst), "l"(src));
}
__device__ __forceinline__ void cp_commit() {
    asm volatile("cp.async.commit_group;" ::: "memory");
}
__device__ __forceinline__ void cp_wait0() {
    asm volatile("cp.async.wait_group 0;" ::: "memory");
}
__device__ __forceinline__ void cp_wait1() {
    asm volatile("cp.async.wait_group 1;" ::: "memory");
}

// ---- legacy mma.sync path (conv1 edge GEMM + fallbacks) ----
__device__ __forceinline__ void ldsm_x4(uint32_t& r0, uint32_t& r1, uint32_t& r2, uint32_t& r3,
                                        uint32_t addr) {
    asm volatile("ldmatrix.sync.aligned.m8n8.x4.shared.b16 {%0,%1,%2,%3}, [%4];"
                 : "=r"(r0), "=r"(r1), "=r"(r2), "=r"(r3) : "r"(addr));
}

__device__ __forceinline__ void mma16816(float c[4], const uint32_t a[4], const uint32_t b[2]) {
    asm volatile(
        "mma.sync.aligned.m16n8k16.row.col.f32.f16.f16.f32 "
        "{%0,%1,%2,%3},{%4,%5,%6,%7},{%8,%9},{%0,%1,%2,%3};"
        : "+f"(c[0]), "+f"(c[1]), "+f"(c[2]), "+f"(c[3])
        : "r"(a[0]), "r"(a[1]), "r"(a[2]), "r"(a[3]), "r"(b[0]), "r"(b[1]));
}

__device__ __forceinline__ void mma_chunk(const __half* As, const __half* Bs, int lane,
                                          int wm, int wn, float c[4][4][4]) {
#pragma unroll
    for (int ks = 0; ks < 2; ks++) {
        const int k0 = ks * 16;
        uint32_t a[4][4];
#pragma unroll
        for (int mf = 0; mf < 4; mf++) {
            const __half* ap = As + (wm * 64 + mf * 16 + (lane & 15)) * 40 + k0 + ((lane >> 4) << 3);
            ldsm_x4(a[mf][0], a[mf][1], a[mf][2], a[mf][3], smem_u32(ap));
        }
        uint32_t b[4][2];
#pragma unroll
        for (int p = 0; p < 2; p++) {
            const __half* bp = Bs + (wn * 32 + p * 16 + (lane & 7) + ((lane >> 4) << 3)) * 40
                               + k0 + (((lane >> 3) & 1) << 3);
            uint32_t r0, r1, r2, r3;
            ldsm_x4(r0, r1, r2, r3, smem_u32(bp));
            b[2 * p][0] = r0; b[2 * p][1] = r1; b[2 * p + 1][0] = r2; b[2 * p + 1][1] = r3;
        }
#pragma unroll
        for (int mf = 0; mf < 4; mf++)
#pragma unroll
            for (int nf = 0; nf < 4; nf++)
                mma16816(c[mf][nf], a[mf], b[nf]);
    }
}

__device__ __forceinline__ void mma_chunk_abb(const __half* As, const __half* Bh_,
                                              const __half* Bl_, int lane, int wm, int wn,
                                              float c[4][4][4]) {
#pragma unroll
    for (int ks = 0; ks < 2; ks++) {
        const int k0 = ks * 16;
        uint32_t a[4][4];
#pragma unroll
        for (int mf = 0; mf < 4; mf++) {
            const __half* ap = As + (wm * 64 + mf * 16 + (lane & 15)) * 40 + k0 + ((lane >> 4) << 3);
            ldsm_x4(a[mf][0], a[mf][1], a[mf][2], a[mf][3], smem_u32(ap));
        }
        uint32_t bh[4][2], bl[4][2];
#pragma unroll
        for (int p = 0; p < 2; p++) {
            int boff = (wn * 32 + p * 16 + (lane & 7) + ((lane >> 4) << 3)) * 40
                       + k0 + (((lane >> 3) & 1) << 3);
            uint32_t r0, r1, r2, r3;
            ldsm_x4(r0, r1, r2, r3, smem_u32(Bh_ + boff));
            bh[2 * p][0] = r0; bh[2 * p][1] = r1; bh[2 * p + 1][0] = r2; bh[2 * p + 1][1] = r3;
            ldsm_x4(r0, r1, r2, r3, smem_u32(Bl_ + boff));
            bl[2 * p][0] = r0; bl[2 * p][1] = r1; bl[2 * p + 1][0] = r2; bl[2 * p + 1][1] = r3;
        }
#pragma unroll
        for (int mf = 0; mf < 4; mf++)
#pragma unroll
            for (int nf = 0; nf < 4; nf++)
                mma16816(c[mf][nf], a[mf], bh[nf]);
#pragma unroll
        for (int mf = 0; mf < 4; mf++)
#pragma unroll
            for (int nf = 0; nf < 4; nf++)
                mma16816(c[mf][nf], a[mf], bl[nf]);
    }
}

#if HAS_TC
// ---- tcgen05 helpers (arch-specific pass only) ----
__device__ __forceinline__ uint32_t elect_one_pred() {
    uint32_t pred;
    asm volatile(
        "{\n\t.reg .pred p;\n\telect.sync _|p, 0xFFFFFFFF;\n\t"
        "selp.b32 %0, 1, 0, p;\n\t}" : "=r"(pred));
    return pred;
}

// SW64 K-major descriptor: layout=4, version=1 (Blackwell), SBO=32, LBO=1
static constexpr uint64_t SMEM_DESC_BASE_SW64 =
    (uint64_t(4) << 61) | (uint64_t(1) << 46) | (uint64_t(32) << 32) | (uint64_t(1) << 16);

__device__ __forceinline__ uint64_t make_desc64(uint32_t addr) {
    return SMEM_DESC_BASE_SW64 | ((uint64_t)(addr >> 4) & 0x3FFF);
}

__device__ __forceinline__ void mma_f16_ss_cg1(uint32_t d_tmem, uint64_t a_desc, uint64_t b_desc,
                                               uint32_t idesc, uint32_t en) {
    asm volatile(
        "{\n\t.reg .pred p;\n\tsetp.ne.u32 p, %5, 0;\n\t"
        "tcgen05.mma.cta_group::1.kind::f16 [%0], %1, %2, %3, {%4,%4,%4,%4}, p;\n\t}"
        :: "r"(d_tmem), "l"(a_desc), "l"(b_desc), "r"(idesc), "r"(0u), "r"(en)
        : "memory");
}

__device__ __forceinline__ void mbar_init(uint32_t addr, uint32_t cnt) {
    asm volatile("mbarrier.init.shared.b64 [%0], %1;" :: "r"(addr), "r"(cnt) : "memory");
}

__device__ __forceinline__ void mbar_wait(uint32_t addr, uint32_t parity) {
    asm volatile(
        "{\n\t.reg .pred P1;\n\t"
        "WAIT_%=:\n\t"
        "mbarrier.try_wait.parity.acquire.cta.shared::cta.b64 P1, [%0], %1, 0x989680;\n\t"
        "@P1 bra.uni DONE_%=;\n\t"
        "bra.uni WAIT_%=;\n\t"
        "DONE_%=:\n\t}"
        :: "r"(addr), "r"(parity) : "memory");
}

// TMEM 32x32b.x32 load into regs[32]
#define LDTM32(regs, addr)                                                              \
    asm volatile(                                                                       \
        "tcgen05.ld.sync.aligned.32x32b.x32.b32 "                                       \
        "{%0,%1,%2,%3,%4,%5,%6,%7,%8,%9,%10,%11,%12,%13,%14,%15,"                       \
        "%16,%17,%18,%19,%20,%21,%22,%23,%24,%25,%26,%27,%28,%29,%30,%31}, [%32];"      \
        : "=r"(regs[0]), "=r"(regs[1]), "=r"(regs[2]), "=r"(regs[3]),                   \
          "=r"(regs[4]), "=r"(regs[5]), "=r"(regs[6]), "=r"(regs[7]),                   \
          "=r"(regs[8]), "=r"(regs[9]), "=r"(regs[10]), "=r"(regs[11]),                 \
          "=r"(regs[12]), "=r"(regs[13]), "=r"(regs[14]), "=r"(regs[15]),               \
          "=r"(regs[16]), "=r"(regs[17]), "=r"(regs[18]), "=r"(regs[19]),               \
          "=r"(regs[20]), "=r"(regs[21]), "=r"(regs[22]), "=r"(regs[23]),               \
          "=r"(regs[24]), "=r"(regs[25]), "=r"(regs[26]), "=r"(regs[27]),               \
          "=r"(regs[28]), "=r"(regs[29]), "=r"(regs[30]), "=r"(regs[31])                \
        : "r"(addr))
#endif  // HAS_TC

// ------------------------- small kernels -------------------------
__global__ void k_init() {
    int idx = blockIdx.x * blockDim.x + threadIdx.x;
    const float NEGINF = __int_as_float(0xff800000);
    if (idx < NN) g_deg[idx] = 0;
    if (idx < NN * 128) g_agg1[idx] = NEGINF;
    if (idx < NN * 1024) g_agg2[idx] = NEGINF;
}

__global__ void k_hist(const int* __restrict__ ei) {
    int e = blockIdx.x * blockDim.x + threadIdx.x;
    if (e < NE) atomicAdd(&g_deg[ei[NE + e]], 1);
}

__global__ void k_scan() {
    __shared__ int part[1024];
    int t = threadIdx.x;
    int base = t * 10;
    int loc[10];
    int s = 0;
#pragma unroll
    for (int i = 0; i < 10; i++) {
        int idx = base + i;
        int v = (idx < NN) ? g_deg[idx] : 0;
        loc[i] = s; s += v;
    }
    part[t] = s;
    __syncthreads();
    for (int off = 1; off < 1024; off <<= 1) {
        int v = 0;
        if (t >= off) v = part[t - off];
        __syncthreads();
        if (t >= off) part[t] += v;
        __syncthreads();
    }
    int excl = (t == 0) ? 0 : part[t - 1];
#pragma unroll
    for (int i = 0; i < 10; i++) {
        int idx = base + i;
        if (idx < NN) g_cur[idx] = excl + loc[i];
    }
}

__global__ void k_scatter(const int* __restrict__ ei) {
    int e = blockIdx.x * blockDim.x + threadIdx.x;
    if (e < NE) {
        int d = ei[NE + e];
        int p = atomicAdd(&g_cur[d], 1);
        g_srcs[p] = ei[e];
        g_dsts[p] = d;
    }
}

// W[K,F] fp32 -> split Wt[F,2K] (hi | lo), smem-tiled for coalesced writes
__global__ void k_cvtT_split_t(const float* __restrict__ W, __half* __restrict__ Wt,
                               int K, int F) {
    __shared__ float tile[32][33];
    int kt = blockIdx.y * 32, ft = blockIdx.x * 32;
    int tx = threadIdx.x, ty = threadIdx.y;  // 32 x 8
#pragma unroll
    for (int i = 0; i < 32; i += 8)
        tile[ty + i][tx] = W[(size_t)(kt + ty + i) * F + ft + tx];
    __syncthreads();
#pragma unroll
    for (int i = 0; i < 32; i += 8) {
        int f = ft + ty + i, k = kt + tx;
        float v = tile[tx][ty + i];
        __half hi = __float2half(v);
        Wt[(size_t)f * 2 * K + k] = hi;
        Wt[(size_t)f * 2 * K + K + k] = __float2half(v - __half2float(hi));
    }
}

// W (row-major [K, ld], use cols [0,F)) -> SW64 tcgen05 tiles [y(F/256)][ch(K/32)][hi|lo]
__global__ void k_cvt_wsw(const float* __restrict__ W, __half* __restrict__ out,
                          int K, int F, int ld) {
    int idx = blockIdx.x * blockDim.x + threadIdx.x;
    if (idx >= K * F) return;
    int k = idx / F, f = idx % F;
    float v = W[(size_t)k * ld + f];
    __half hi = __float2half(v);
    __half lo = __float2half(v - __half2float(hi));
    int y = f >> 8, r = f & 255, ch = k >> 5, c = k & 31;
    uint32_t bo = (uint32_t)(r * 64 + c * 2);
    uint32_t sw = bo ^ ((bo >> 3) & 0x30);
    size_t base = ((size_t)y * (K / 32) + ch) * 16384;
    out[base + (sw >> 1)] = hi;
    out[base + 8192 + (sw >> 1)] = lo;
}

// conv1 node precompute (fp32): A1 = x·(Wx+Wp)+b ; B1 = x·Wp
__global__ void k_precomp1(const float* __restrict__ x, const float* __restrict__ w,
                           const float* __restrict__ b) {
    int idx = blockIdx.x * blockDim.x + threadIdx.x;
    if (idx >= NN * 64) return;
    int n = idx >> 6, f = idx & 63;
    float x0 = x[2 * n], x1 = x[2 * n + 1];
    float w0 = w[f], w1 = w[64 + f], w2 = w[128 + f], w3 = w[192 + f];
    g_A1f[idx] = x0 * (w0 + w2) + x1 * (w1 + w3) + b[f];
    g_B1f[idx] = x0 * w2 + x1 * w3;
}

// conv2 pos precompute: D2 = x·Wp (rows 512,513 of l2w1 [514,1024])
__global__ void k_precompD2(const float* __restrict__ x, const float* __restrict__ l2w1) {
    int idx = blockIdx.x * blockDim.x + threadIdx.x;
    if (idx >= NN * 1024) return;
    int n = idx >> 10, f = idx & 1023;
    g_D2f[idx] = x[2 * n] * l2w1[512 * 1024 + f] + x[2 * n + 1] * l2w1[513 * 1024 + f];
}

// edge activations: ACT[p] = split(leaky(C2[src[p]] - D2[dst[p]])) — one block per edge
__global__ void __launch_bounds__(256)
k_edge_act(const float* __restrict__ C, const float* __restrict__ D) {
    int p = blockIdx.x;
    int s = g_srcs[p], d = g_dsts[p];
    int t = threadIdx.x;
    const float4 cv = *(const float4*)(C + (size_t)s * 1024 + t * 4);
    const float4 dv = *(const float4*)(D + (size_t)d * 1024 + t * 4);
    float m0 = leaky1f(cv.x - dv.x), m1 = leaky1f(cv.y - dv.y);
    float m2 = leaky1f(cv.z - dv.z), m3 = leaky1f(cv.w - dv.w);
    __half h0 = __float2half(m0), h1 = __float2half(m1);
    __half h2 = __float2half(m2), h3 = __float2half(m3);
    __half* base = g_ACT + (size_t)p * 2048 + t * 4;
    *(__half2*)(base) = __halves2half2(h0, h1);
    *(__half2*)(base + 2) = __halves2half2(h2, h3);
    *(__half2*)(base + 1024) = __halves2half2(__float2half(m0 - __half2float(h0)),
                                              __float2half(m1 - __half2float(h1)));
    *(__half2*)(base + 1026) = __halves2half2(__float2half(m2 - __half2float(h2)),
                                              __float2half(m3 - __half2float(h3)));
}

// agg fp32 -> hi/lo pair buffer [NN, 2F]
__global__ void k_fin_hl(const float* __restrict__ agg, __half* __restrict__ out,
                         int logF, int total) {
    int idx = blockIdx.x * blockDim.x + threadIdx.x;
    if (idx >= total) return;
    int F = 1 << logF;
    int n = idx >> logF, f = idx & (F - 1);
    float v = agg[idx];
    if (v < -1e30f) v = 0.0f;
    __half hi = __float2half(v);
    out[(size_t)n * 2 * F + f] = hi;
    out[(size_t)n * 2 * F + F + f] = __float2half(v - __half2float(hi));
}

// two-stage deterministic BN stats
__global__ void k_stats_partial(const float* __restrict__ P, int F) {
    int c = blockIdx.x * 128 + threadIdx.x;
    int r0 = blockIdx.y * 128;
    int r1 = r0 + 128; if (r1 > NN) r1 = NN;
    float s = 0.f, q = 0.f;
    for (int r = r0; r < r1; r++) {
        float v = P[(size_t)r * F + c];
        s += v; q += v * v;
    }
    g_part[(size_t)blockIdx.y * F + c] = s;
    g_partq[(size_t)blockIdx.y * F + c] = q;
}

__global__ void k_stats_final(int F) {
    int c = blockIdx.x * 128 + threadIdx.x;
    if (c >= F) return;
    float s = 0.f, q = 0.f;
    for (int t = 0; t < MTILES; t++) {
        s += g_part[(size_t)t * F + c];
        q += g_partq[(size_t)t * F + c];
    }
    float mu = s / NN;
    float var = fmaxf(q / NN - mu * mu, 0.0f);
    g_mu[c] = mu;
    g_rs[c] = rsqrtf(var + 1e-5f);
}

// BN -> hi/lo pair buffer
__global__ void k_norm_hl(const float* __restrict__ P, const float* __restrict__ gamma,
                          const float* __restrict__ beta, __half* __restrict__ out,
                          int logF, int total) {
    int idx = blockIdx.x * blockDim.x + threadIdx.x;
    if (idx >= total) return;
    int F = 1 << logF;
    int n = idx >> logF, f = idx & (F - 1);
    float v = gamma[f] * (P[idx] - g_mu[f]) * g_rs[f] + beta[f];
    __half hi = __float2half(v);
    out[(size_t)n * 2 * F + f] = hi;
    out[(size_t)n * 2 * F + F + f] = __float2half(v - __half2float(hi));
}

__global__ void k_norm_float(const float* __restrict__ P, const float* __restrict__ gamma,
                             const float* __restrict__ beta, float* __restrict__ out,
                             int mask, int total) {
    int idx = blockIdx.x * blockDim.x + threadIdx.x;
    if (idx < total) {
        int f = idx & mask;
        out[idx] = gamma[f] * (P[idx] - g_mu[f]) * g_rs[f] + beta[f];
    }
}

// ------------------------- legacy edge GEMM (conv1, small) -------------------------
template <int KB, int NWN>
__global__ void __launch_bounds__(NWN * 64, 1)
k_edge_gemm(const float* __restrict__ Crow, const float* __restrict__ Drow,
            const __half* __restrict__ Wt, const float* __restrict__ bias,
            float* __restrict__ agg) {
    constexpr int NT = NWN * 32;
    constexpr int T = NWN * 64;
    extern __shared__ __align__(16) char dsm[];
    __half* As_hi = (__half*)dsm;
    __half* As_lo = As_hi + 128 * 40;
    __half* Bs_hi = As_lo + 128 * 40;
    __half* Bs_lo = Bs_hi + NT * 40;
    float* Cs = (float*)dsm;
    __shared__ int s_src[128];
    __shared__ int s_dst[128];

    const int tid = threadIdx.x;
    const int lane = tid & 31;
    const int warp = tid >> 5;
    const int wm = warp & 1, wn = warp >> 1;
    const int e0 = blockIdx.x * 128;
    const int colg0 = blockIdx.y * NT;
    const int F = gridDim.y * NT;

    if (tid < 128) {
        s_src[tid] = g_srcs[e0 + tid];
        s_dst[tid] = g_dsts[e0 + tid];
    }
    __syncthreads();

    float c[4][4][4];
#pragma unroll
    for (int i = 0; i < 4; i++)
#pragma unroll
        for (int j = 0; j < 4; j++)
#pragma unroll
            for (int k = 0; k < 4; k++) c[i][j][k] = 0.0f;

    for (int k0 = 0; k0 < KB; k0 += 32) {
#pragma unroll
        for (int i = 0; i < 1024 / T; i++) {
            int idx = tid + i * T;
            int r = idx >> 3, s = idx & 7;
            const float4 cv = *(const float4*)(Crow + (size_t)s_src[r] * KB + k0 + s * 4);
            const float4 dv = *(const float4*)(Drow + (size_t)s_dst[r] * KB + k0 + s * 4);
            float m0 = leaky1f(cv.x - dv.x), m1 = leaky1f(cv.y - dv.y);
            float m2 = leaky1f(cv.z - dv.z), m3 = leaky1f(cv.w - dv.w);
            __half h0 = __float2half(m0), h1 = __float2half(m1);
            __half h2 = __float2half(m2), h3 = __float2half(m3);
            int off = r * 40 + s * 4;
            *(__half2*)&As_hi[off] = __halves2half2(h0, h1);
            *(__half2*)&As_hi[off + 2] = __halves2half2(h2, h3);
            *(__half2*)&As_lo[off] = __halves2half2(__float2half(m0 - __half2float(h0)),
                                                    __float2half(m1 - __half2float(h1)));
            *(__half2*)&As_lo[off + 2] = __halves2half2(__float2half(m2 - __half2float(h2)),
                                                        __float2half(m3 - __half2float(h3)));
        }
#pragma unroll
        for (int i = 0; i < NT * 4 / T; i++) {
            int idx = tid + i * T;
            int r = idx >> 2, s = idx & 3;
            const __half* wrow = Wt + (size_t)(colg0 + r) * 2 * KB + k0 + s * 8;
            *(int4*)&Bs_hi[r * 40 + s * 8] = *(const int4*)wrow;
            *(int4*)&Bs_lo[r * 40 + s * 8] = *(const int4*)(wrow + KB);
        }
        __syncthreads();
        mma_chunk_abb(As_hi, Bs_hi, Bs_lo, lane, wm, wn, c);
        mma_chunk(As_lo, Bs_hi, lane, wm, wn, c);
        __syncthreads();
    }

#pragma unroll
    for (int mf = 0; mf < 4; mf++) {
#pragma unroll
        for (int nf = 0; nf < 4; nf++) {
            int rl = wm * 64 + mf * 16 + (lane >> 2);
            int cl = wn * 32 + nf * 8 + (lane & 3) * 2;
            float b0 = bias[colg0 + cl], b1 = bias[colg0 + cl + 1];
#pragma unroll
            for (int h = 0; h < 2; h++) {
                float v0 = leaky1f(c[mf][nf][2 * h + 0] + b0);
                float v1 = leaky1f(c[mf][nf][2 * h + 1] + b1);
                *(float2*)&Cs[(rl + h * 8) * (NT + 2) + cl] = make_float2(v0, v1);
            }
        }
    }
    __syncthreads();

    {
        int col = tid & (NT - 1);
        int rbeg = (tid >= NT) ? 64 : 0;
        float cur = __int_as_float(0xff800000);
        int curd = s_dst[rbeg];
        for (int r = rbeg; r < rbeg + 64; r++) {
            int d = s_dst[r];
            if (d != curd) {
                atomicMaxF(&agg[(size_t)curd * F + colg0 + col], cur);
                cur = __int_as_float(0xff800000);
                curd = d;
            }
            cur = fmaxf(cur, Cs[r * (NT + 2) + col]);
        }
        atomicMaxF(&agg[(size_t)curd * F + colg0 + col], cur);
    }
}

// ------------------------- shared tile sizes -------------------------
#define EK_SLOT 65536
#define EK_SMEM (3 * EK_SLOT + 1024)
#define LSTG    61440

// ------------------------- conv2 edge GEMM: tcgen05, M=256 shared-W -------------------------
__global__ void __launch_bounds__(512, 1)
k_edge_tc(const float* __restrict__ bias, float* __restrict__ agg) {
    extern __shared__ char dsm_raw[];
    char* dsm0 = (char*)(((uintptr_t)dsm_raw + 1023) & ~(uintptr_t)1023);
    __shared__ int s_dst[256];

    const int tid = threadIdx.x;
    const int wid = tid >> 5;
    const int lane = tid & 31;
    const int e0 = blockIdx.x * 256;
    const int y = blockIdx.y;
    const int colg0 = y * 256;

    if (tid < 256) s_dst[tid] = g_dsts[e0 + tid];

    float* Cs = (float*)dsm0;  // 128 x 258 fp32 per tile pass

#if HAS_TC
    __shared__ __align__(8) uint64_t s_mbar[3];
    __shared__ uint32_t s_tmem;
    const uint32_t sbase = smem_u32(dsm0);

    if (tid == 0) {
        mbar_init(smem_u32(&s_mbar[0]), 1);
        mbar_init(smem_u32(&s_mbar[1]), 1);
        mbar_init(smem_u32(&s_mbar[2]), 1);
    }
    if (wid == 0) {
        asm volatile("tcgen05.alloc.cta_group::1.sync.aligned.shared::cta.b32 [%0], %1;"
                     :: "r"(smem_u32(&s_tmem)), "r"(512u) : "memory");
    }
    __syncthreads();
    const uint32_t tmem = s_tmem;

    const uint32_t IDESC = (1u << 4) | (32u << 17) | (8u << 24);
    int wp[3] = {0, 0, 0};

    auto load_chunk = [&](int ch) {
        const uint32_t su = sbase + (ch % 3) * EK_SLOT;
        const int k0h = ch * 32;
        int r = tid >> 2, s = tid & 3;
        uint32_t bo = (uint32_t)(r * 64 + s * 16);
        uint32_t sw = bo ^ ((bo >> 3) & 0x30);
#pragma unroll
        for (int t = 0; t < 2; t++) {
            const __half* src = g_ACT + (size_t)(e0 + t * 128 + r) * 2048 + k0h + s * 8;
            cp16(su + t * 16384 + sw, src);
            cp16(su + t * 16384 + 8192 + sw, src + 1024);
        }
        const char* ws = (const char*)(g_W2sw + ((size_t)y * 32 + ch) * 16384);
#pragma unroll
        for (int i = 0; i < 4; i++) {
            int j = tid + i * 512;
            cp16(su + 32768 + j * 16, ws + j * 16);
        }
        cp_commit();
    };

    load_chunk(0);

#pragma unroll 1
    for (int ch = 0; ch < 32; ch++) {
        if (ch + 1 < 32) {
            int c = ch + 1, sl = c % 3;
            if (c >= 3) { mbar_wait(smem_u32(&s_mbar[sl]), wp[sl] & 1); wp[sl]++; }
            load_chunk(c);
            cp_wait1();
        } else {
            cp_wait0();
        }
        asm volatile("fence.proxy.async.shared::cta;" ::: "memory");
        __syncthreads();
        if (wid == 0 && elect_one_pred()) {
            const uint32_t su = sbase + (ch % 3) * EK_SLOT;
            uint64_t a0h = make_desc64(su);
            uint64_t a0l = make_desc64(su + 8192);
            uint64_t a1h = make_desc64(su + 16384);
            uint64_t a1l = make_desc64(su + 24576);
            uint64_t wh  = make_desc64(su + 32768);
            uint64_t wl  = make_desc64(su + 49152);
#pragma unroll
            for (int ks = 0; ks < 2; ks++) {
                uint32_t en = (ch == 0 && ks == 0) ? 0u : 1u;
                mma_f16_ss_cg1(tmem,       a0h + ks * 2, wh + ks * 2, IDESC, en);
                mma_f16_ss_cg1(tmem,       a0l + ks * 2, wh + ks * 2, IDESC, 1u);
                mma_f16_ss_cg1(tmem,       a0h + ks * 2, wl + ks * 2, IDESC, 1u);
                mma_f16_ss_cg1(tmem + 256, a1h + ks * 2, wh + ks * 2, IDESC, en);
                mma_f16_ss_cg1(tmem + 256, a1l + ks * 2, wh + ks * 2, IDESC, 1u);
                mma_f16_ss_cg1(tmem + 256, a1h + ks * 2, wl + ks * 2, IDESC, 1u);
            }
            asm volatile(
                "tcgen05.commit.cta_group::1.mbarrier::arrive::one.shared::cluster.b64 [%0];"
                :: "r"(smem_u32(&s_mbar[ch % 3])) : "memory");
        }
    }
    mbar_wait(smem_u32(&s_mbar[0]), wp[0] & 1);
    mbar_wait(smem_u32(&s_mbar[1]), wp[1] & 1);
    mbar_wait(smem_u32(&s_mbar[2]), wp[2] & 1);
    asm volatile("tcgen05.fence::after_thread_sync;" ::: "memory");
    __syncthreads();

#pragma unroll 1
    for (int t = 0; t < 2; t++) {
        // parallel epilogue: 4 warpgroups x 2 col-chunks each (subpartition = wid & 3)
        {
            int sub = wid & 3, wg = wid >> 2;
            int row = sub * 32 + lane;
#pragma unroll
            for (int q = 0; q < 2; q++) {
                int cc = wg * 2 + q;
                uint32_t regs[32];
                LDTM32(regs, tmem + t * 256 + cc * 32);
                asm volatile("tcgen05.wait::ld.sync.aligned;" ::: "memory");
#pragma unroll
                for (int j = 0; j < 32; j++) {
                    int col = cc * 32 + j;
                    Cs[row * 258 + col] = leaky1f(__uint_as_float(regs[j]) + bias[colg0 + col]);
                }
            }
            asm volatile("tcgen05.fence::before_thread_sync;" ::: "memory");
        }
        __syncthreads();
        {
            int col = tid & 255;
            int rbeg = (tid >= 256) ? 64 : 0;
            float cur = __int_as_float(0xff800000);
            int curd = s_dst[t * 128 + rbeg];
#pragma unroll 1
            for (int r = rbeg; r < rbeg + 64; r++) {
                int d = s_dst[t * 128 + r];
                if (d != curd) {
                    atomicMaxF(&agg[(size_t)curd * 1024 + colg0 + col], cur);
                    cur = __int_as_float(0xff800000);
                    curd = d;
                }
                cur = fmaxf(cur, Cs[r * 258 + col]);
            }
            atomicMaxF(&agg[(size_t)curd * 1024 + colg0 + col], cur);
        }
        __syncthreads();
    }

    if (wid == 0) {
        asm volatile("tcgen05.relinquish_alloc_permit.cta_group::1.sync.aligned;");
        asm volatile("tcgen05.dealloc.cta_group::1.sync.aligned.b32 %0, %1;"
                     :: "r"(tmem), "r"(512u));
    }
#else
    // legacy fallback: two 128-edge tiles sequentially
    const int wm = wid & 1, wn = wid >> 1;
    const uint32_t sb0 = smem_u32(dsm0);

#pragma unroll 1
    for (int t = 0; t < 2; t++) {
        __syncthreads();
        float c[4][4][4];
#pragma unroll
        for (int i = 0; i < 4; i++)
#pragma unroll
            for (int j = 0; j < 4; j++)
#pragma unroll
                for (int k = 0; k < 4; k++) c[i][j][k] = 0.0f;

        auto load_chunk = [&](int ch) {
            const int k0 = ch * 32;
            const uint32_t sb = sb0 + (ch % 3) * LSTG;
            int r = tid >> 2, s = tid & 3;
            const __half* asrc = g_ACT + (size_t)(e0 + t * 128 + r) * 2048 + k0 + s * 8;
            cp16(sb + r * 80 + s * 16, asrc);
            cp16(sb + 10240 + r * 80 + s * 16, asrc + 1024);
#pragma unroll
            for (int i = 0; i < 2; i++) {
                int idx = tid + i * 512;
                int wr = idx >> 2, ws_ = idx & 3;
                const __half* wsrc = g_W_l2w2 + (size_t)(colg0 + wr) * 2048 + k0 + ws_ * 8;
                cp16(sb + 20480 + wr * 80 + ws_ * 16, wsrc);
                cp16(sb + 40960 + wr * 80 + ws_ * 16, wsrc + 1024);
            }
            cp_commit();
        };

        load_chunk(0);
#pragma unroll 1
        for (int ch = 0; ch < 32; ch++) {
            if (ch + 1 < 32) { load_chunk(ch + 1); cp_wait1(); }
            else             { cp_wait0(); }
            __syncthreads();
            __half* Ah = (__half*)(dsm0 + (ch % 3) * LSTG);
            __half* Al = Ah + 5120;
            __half* Bh = Ah + 10240;
            __half* Bl = Ah + 20480;
            mma_chunk_abb(Ah, Bh, Bl, lane, wm, wn, c);
            mma_chunk(Al, Bh, lane, wm, wn, c);
        }
        __syncthreads();

#pragma unroll
        for (int mf = 0; mf < 4; mf++) {
#pragma unroll
            for (int nf = 0; nf < 4; nf++) {
                int rl = wm * 64 + mf * 16 + (lane >> 2);
                int cl = wn * 32 + nf * 8 + (lane & 3) * 2;
                float b0 = bias[colg0 + cl], b1 = bias[colg0 + cl + 1];
#pragma unroll
                for (int h = 0; h < 2; h++) {
                    float v0 = leaky1f(c[mf][nf][2 * h + 0] + b0);
                    float v1 = leaky1f(c[mf][nf][2 * h + 1] + b1);
                    *(float2*)&Cs[(rl + h * 8) * 258 + cl] = make_float2(v0, v1);
                }
            }
        }
        __syncthreads();
        {
            int col = tid & 255;
            int rbeg = (tid >= 256) ? 64 : 0;
            float cur = __int_as_float(0xff800000);
            int curd = s_dst[t * 128 + rbeg];
#pragma unroll 1
            for (int r = rbeg; r < rbeg + 64; r++) {
                int d = s_dst[t * 128 + r];
                if (d != curd) {
                    atomicMaxF(&agg[(size_t)curd * 1024 + colg0 + col], cur);
                    cur = __int_as_float(0xff800000);
                    curd = d;
                }
                cur = fmaxf(cur, Cs[r * 258 + col]);
            }
            atomicMaxF(&agg[(size_t)curd * 1024 + colg0 + col], cur);
        }
        __syncthreads();
    }
#endif
}

// ------------------------- dense node GEMM: tcgen05, 256 rows x 256 cols -------------------------
template <int KB, int MODE>
__global__ void __launch_bounds__(512, 1)
k_ngemm_tc(const __half* __restrict__ A, const __half* __restrict__ Wsw,
           const __half* __restrict__ Wleg, const float* __restrict__ bias,
           __half* __restrict__ outH, float* __restrict__ outF,
           const float* __restrict__ extra, int M) {
    extern __shared__ char dsm_raw[];
    char* dsm0 = (char*)(((uintptr_t)dsm_raw + 1023) & ~(uintptr_t)1023);

    const int tid = threadIdx.x;
    const int wid = tid >> 5;
    const int lane = tid & 31;
    const int tileM = blockIdx.x;   // 256-row tiles
    const int y = blockIdx.y;
    const int colg0 = y * 256;
    const int F = gridDim.y * 256;
    constexpr int NCH = KB / 32;

    float* Cs = (float*)dsm0;  // 128 x 258

#if HAS_TC
    __shared__ __align__(8) uint64_t s_mbar[3];
    __shared__ uint32_t s_tmem;
    const uint32_t sbase = smem_u32(dsm0);

    if (tid == 0) {
        mbar_init(smem_u32(&s_mbar[0]), 1);
        mbar_init(smem_u32(&s_mbar[1]), 1);
        mbar_init(smem_u32(&s_mbar[2]), 1);
    }
    if (wid == 0) {
        asm volatile("tcgen05.alloc.cta_group::1.sync.aligned.shared::cta.b32 [%0], %1;"
                     :: "r"(smem_u32(&s_tmem)), "r"(512u) : "memory");
    }
    __syncthreads();
    const uint32_t tmem = s_tmem;

    const uint32_t IDESC = (1u << 4) | (32u << 17) | (8u << 24);
    int wp[3] = {0, 0, 0};

    auto load_chunk = [&](int ch) {
        const uint32_t su = sbase + (ch % 3) * EK_SLOT;
        const int k0h = ch * 32;
        int r = tid >> 2, s = tid & 3;
        uint32_t bo = (uint32_t)(r * 64 + s * 16);
        uint32_t sw = bo ^ ((bo >> 3) & 0x30);
#pragma unroll
        for (int t = 0; t < 2; t++) {
            int rg = tileM * 256 + t * 128 + r;
            if (rg >= M) rg = M - 1;
            const __half* src = A + (size_t)rg * 2 * KB + k0h + s * 8;
            cp16(su + t * 16384 + sw, src);
            cp16(su + t * 16384 + 8192 + sw, src + KB);
        }
        const char* ws = (const char*)(Wsw + ((size_t)y * NCH + ch) * 16384);
#pragma unroll
        for (int i = 0; i < 4; i++) {
            int j = tid + i * 512;
            cp16(su + 32768 + j * 16, ws + j * 16);
        }
        cp_commit();
    };

    load_chunk(0);

#pragma unroll 1
    for (int ch = 0; ch < NCH; ch++) {
        if (ch + 1 < NCH) {
            int c = ch + 1, sl = c % 3;
            if (c >= 3) { mbar_wait(smem_u32(&s_mbar[sl]), wp[sl] & 1); wp[sl]++; }
            load_chunk(c);
            cp_wait1();
        } else {
            cp_wait0();
        }
        asm volatile("fence.proxy.async.shared::cta;" ::: "memory");
        __syncthreads();
        if (wid == 0 && elect_one_pred()) {
            const uint32_t su = sbase + (ch % 3) * EK_SLOT;
            uint64_t a0h = make_desc64(su);
            uint64_t a0l = make_desc64(su + 8192);
            uint64_t a1h = make_desc64(su + 16384);
            uint64_t a1l = make_desc64(su + 24576);
            uint64_t wh  = make_desc64(su + 32768);
            uint64_t wl  = make_desc64(su + 49152);
#pragma unroll
            for (int ks = 0; ks < 2; ks++) {
                uint32_t en = (ch == 0 && ks == 0) ? 0u : 1u;
                mma_f16_ss_cg1(tmem,       a0h + ks * 2, wh + ks * 2, IDESC, en);
                mma_f16_ss_cg1(tmem,       a0l + ks * 2, wh + ks * 2, IDESC, 1u);
                mma_f16_ss_cg1(tmem,       a0h + ks * 2, wl + ks * 2, IDESC, 1u);
                mma_f16_ss_cg1(tmem + 256, a1h + ks * 2, wh + ks * 2, IDESC, en);
                mma_f16_ss_cg1(tmem + 256, a1l + ks * 2, wh + ks * 2, IDESC, 1u);
                mma_f16_ss_cg1(tmem + 256, a1h + ks * 2, wl + ks * 2, IDESC, 1u);
            }
            asm volatile(
                "tcgen05.commit.cta_group::1.mbarrier::arrive::one.shared::cluster.b64 [%0];"
                :: "r"(smem_u32(&s_mbar[ch % 3])) : "memory");
        }
    }
    mbar_wait(smem_u32(&s_mbar[0]), wp[0] & 1);
    mbar_wait(smem_u32(&s_mbar[1]), wp[1] & 1);
    mbar_wait(smem_u32(&s_mbar[2]), wp[2] & 1);
    asm volatile("tcgen05.fence::after_thread_sync;" ::: "memory");
    __syncthreads();

#pragma unroll 1
    for (int t = 0; t < 2; t++) {
        // parallel epilogue: 4 warpgroups x 2 col-chunks each (subpartition = wid & 3)
        {
            int sub = wid & 3, wg = wid >> 2;
            int row = sub * 32 + lane;
#pragma unroll
            for (int q = 0; q < 2; q++) {
                int cc = wg * 2 + q;
                uint32_t regs[32];
                LDTM32(regs, tmem + t * 256 + cc * 32);
                asm volatile("tcgen05.wait::ld.sync.aligned;" ::: "memory");
#pragma unroll
                for (int j = 0; j < 32; j++) {
                    int col = cc * 32 + j;
                    Cs[row * 258 + col] = __uint_as_float(regs[j]) + bias[colg0 + col];
                }
            }
            asm volatile("tcgen05.fence::before_thread_sync;" ::: "memory");
        }
        __syncthreads();
        // coalesced MODE-specific writes
#pragma unroll 1
        for (int i = tid; i < 128 * 256; i += 512) {
            int r = i >> 8, col = i & 255;
            int rg = tileM * 256 + t * 128 + r;
            if (rg < M) {
                float v = Cs[r * 258 + col];
                int cg = colg0 + col;
                if (MODE == 0) {
                    v = leaky1f(v);
                    __half hi = __float2half(v);
                    outH[(size_t)rg * 2 * F + cg] = hi;
                    outH[(size_t)rg * 2 * F + F + cg] = __float2half(v - __half2float(hi));
                } else if (MODE == 1) {
                    outF[(size_t)rg * F + cg] = leaky1f(leaky1f(v));
                } else {
                    outF[(size_t)rg * F + cg] = v + extra[(size_t)rg * F + cg];
                }
            }
        }
        __syncthreads();
    }

    if (wid == 0) {
        asm volatile("tcgen05.relinquish_alloc_permit.cta_group::1.sync.aligned;");
        asm volatile("tcgen05.dealloc.cta_group::1.sync.aligned.b32 %0, %1;"
                     :: "r"(tmem), "r"(512u));
    }
#else
    // legacy fallback: two 128-row tiles sequentially
    const int wm = wid & 1, wn = wid >> 1;
    const uint32_t sb0 = smem_u32(dsm0);

#pragma unroll 1
    for (int t = 0; t < 2; t++) {
        __syncthreads();
        float c[4][4][4];
#pragma unroll
        for (int i = 0; i < 4; i++)
#pragma unroll
            for (int j = 0; j < 4; j++)
#pragma unroll
                for (int k = 0; k < 4; k++) c[i][j][k] = 0.0f;

        auto load_chunk = [&](int ch) {
            const int k0 = ch * 32;
            const uint32_t sb = sb0 + (ch % 3) * LSTG;
            int r = tid >> 2, s = tid & 3;
            int rg = tileM * 256 + t * 128 + r;
            if (rg >= M) rg = M - 1;
            const __half* asrc = A + (size_t)rg * 2 * KB + k0 + s * 8;
            cp16(sb + r * 80 + s * 16, asrc);
            cp16(sb + 10240 + r * 80 + s * 16, asrc + KB);
#pragma unroll
            for (int i = 0; i < 2; i++) {
                int idx = tid + i * 512;
                int wr = idx >> 2, ws_ = idx & 3;
                const __half* wsrc = Wleg + (size_t)(colg0 + wr) * 2 * KB + k0 + ws_ * 8;
                cp16(sb + 20480 + wr * 80 + ws_ * 16, wsrc);
                cp16(sb + 40960 + wr * 80 + ws_ * 16, wsrc + KB);
            }
            cp_commit();
        };

        load_chunk(0);
#pragma unroll 1
        for (int ch = 0; ch < NCH; ch++) {
            if (ch + 1 < NCH) { load_chunk(ch + 1); cp_wait1(); }
            else              { cp_wait0(); }
            __syncthreads();
            __half* Ah = (__half*)(dsm0 + (ch % 3) * LSTG);
            __half* Al = Ah + 5120;
            __half* Bh = Ah + 10240;
            __half* Bl = Ah + 20480;
            mma_chunk_abb(Ah, Bh, Bl, lane, wm, wn, c);
            mma_chunk(Al, Bh, lane, wm, wn, c);
        }
        __syncthreads();

#pragma unroll
        for (int mf = 0; mf < 4; mf++) {
#pragma unroll
            for (int nf = 0; nf < 4; nf++) {
                int rl = wm * 64 + mf * 16 + (lane >> 2);
                int cl = wn * 32 + nf * 8 + (lane & 3) * 2;
                int cg = colg0 + cl;
                float b0 = bias[cg], b1 = bias[cg + 1];
#pragma unroll
                for (int h = 0; h < 2; h++) {
                    int rg = tileM * 256 + t * 128 + rl + h * 8;
                    if (rg >= M) continue;
                    float v0 = c[mf][nf][2 * h + 0] + b0;
                    float v1 = c[mf][nf][2 * h + 1] + b1;
                    if (MODE == 0) {
                        v0 = leaky1f(v0); v1 = leaky1f(v1);
                        __half h0 = __float2half(v0), h1 = __float2half(v1);
                        *(__half2*)&outH[(size_t)rg * 2 * F + cg] = __halves2half2(h0, h1);
                        *(__half2*)&outH[(size_t)rg * 2 * F + F + cg] = __halves2half2(
                            __float2half(v0 - __half2float(h0)),
                            __float2half(v1 - __half2float(h1)));
                    } else if (MODE == 1) {
                        v0 = leaky1f(leaky1f(v0)); v1 = leaky1f(leaky1f(v1));
                        *(float2*)&outF[(size_t)rg * F + cg] = make_float2(v0, v1);
                    } else {
                        float2 ex = *(const float2*)&extra[(size_t)rg * F + cg];
                        *(float2*)&outF[(size_t)rg * F + cg] = make_float2(v0 + ex.x, v1 + ex.y);
                    }
                }
            }
        }
        __syncthreads();
    }
#endif
}

// ------------------------- host -------------------------
static void* sym(const void* s) {
    void* p = nullptr;
    cudaGetSymbolAddress(&p, s);
    return p;
}

extern "C" void kernel_launch(void* const* d_in, const int* in_sizes, int n_in,
                              void* d_out, int out_size) {
    const float* x    = (const float*)d_in[0];
    const int*   ei   = (const int*)d_in[1];
    const float* l1w1 = (const float*)d_in[3];
    const float* l1b1 = (const float*)d_in[4];
    const float* l1w2 = (const float*)d_in[5];
    const float* l1b2 = (const float*)d_in[6];
    const float* g1w1 = (const float*)d_in[7];
    const float* g1b1 = (const float*)d_in[8];
    const float* g1w2 = (const float*)d_in[9];
    const float* g1b2 = (const float*)d_in[10];
    const float* gamma1 = (const float*)d_in[11];
    const float* beta1  = (const float*)d_in[12];
    const float* l2w1 = (const float*)d_in[13];
    const float* l2b1 = (const float*)d_in[14];
    const float* l2w2 = (const float*)d_in[15];
    const float* l2b2 = (const float*)d_in[16];
    const float* g2w1 = (const float*)d_in[17];
    const float* g2b1 = (const float*)d_in[18];
    const float* g2w2 = (const float*)d_in[19];
    const float* g2b2 = (const float*)d_in[20];
    const float* gamma2 = (const float*)d_in[21];
    const float* beta2  = (const float*)d_in[22];

    float*  A1f    = (float*)sym(g_A1f);
    float*  B1f    = (float*)sym(g_B1f);
    float*  agg1   = (float*)sym(g_agg1);
    __half* agg1hl = (__half*)sym(g_agg1hl);
    __half* T1hl   = (__half*)sym(g_T1hl);
    float*  P1     = (float*)sym(g_P1);
    __half* H1hl   = (__half*)sym(g_H1hl);
    float*  C2f    = (float*)sym(g_C2f);
    float*  D2f    = (float*)sym(g_D2f);
    float*  agg2   = (float*)sym(g_agg2);
    __half* agg2hl = (__half*)sym(g_agg2hl);
    __half* U2hl   = (__half*)sym(g_U2hl);
    float*  P2     = (float*)sym(g_P2);
    __half* W_l1w2 = (__half*)sym(g_W_l1w2);
    __half* W_g1w1 = (__half*)sym(g_W_g1w1);
    __half* W_g1w2 = (__half*)sym(g_W_g1w2);
    __half* W_l2w1 = (__half*)sym(g_W_l2w1);
    __half* W_g2w1 = (__half*)sym(g_W_g2w1);
    __half* W_g2w2 = (__half*)sym(g_W_g2w2);
    __half* Wsw_l2w1 = (__half*)sym(g_Wsw_l2w1);
    __half* Wsw_g2w1 = (__half*)sym(g_Wsw_g2w1);
    __half* Wsw_g2w2 = (__half*)sym(g_Wsw_g2w2);
    __half* Wsw_g1w1 = (__half*)sym(g_Wsw_g1w1);
    __half* Wsw_g1w2 = (__half*)sym(g_Wsw_g1w2);
    __half* W2sw     = (__half*)sym(g_W2sw);

    cudaFuncSetAttribute(k_edge_gemm<64, 4>, cudaFuncAttributeMaxDynamicSharedMemorySize,
                         128 * 130 * 4);
    cudaFuncSetAttribute(k_edge_tc, cudaFuncAttributeMaxDynamicSharedMemorySize, EK_SMEM);
    cudaFuncSetAttribute(k_ngemm_tc<128, 0>, cudaFuncAttributeMaxDynamicSharedMemorySize, EK_SMEM);
    cudaFuncSetAttribute(k_ngemm_tc<256, 1>, cudaFuncAttributeMaxDynamicSharedMemorySize, EK_SMEM);
    cudaFuncSetAttribute(k_ngemm_tc<512, 2>, cudaFuncAttributeMaxDynamicSharedMemorySize, EK_SMEM);
    cudaFuncSetAttribute(k_ngemm_tc<1024, 0>, cudaFuncAttributeMaxDynamicSharedMemorySize, EK_SMEM);
    cudaFuncSetAttribute(k_ngemm_tc<2048, 1>, cudaFuncAttributeMaxDynamicSharedMemorySize, EK_SMEM);

    // CSR build
    k_init<<<(NN * 1024 + 255) / 256, 256>>>();
    k_hist<<<(NE + 255) / 256, 256>>>(ei);
    k_scan<<<1, 1024>>>();
    k_scatter<<<(NE + 255) / 256, 256>>>(ei);

    // weights -> legacy split (conv1 edge + fallbacks) and SW64 tcgen05 tiles
    dim3 tb(32, 8);
    k_cvtT_split_t<<<dim3(128 / 32, 64 / 32), tb>>>(l1w2, W_l1w2, 64, 128);
    k_cvtT_split_t<<<dim3(256 / 32, 128 / 32), tb>>>(g1w1, W_g1w1, 128, 256);
    k_cvtT_split_t<<<dim3(512 / 32, 256 / 32), tb>>>(g1w2, W_g1w2, 256, 512);
    k_cvtT_split_t<<<dim3(1024 / 32, 512 / 32), tb>>>(l2w1, W_l2w1, 512, 1024);
    k_cvtT_split_t<<<dim3(1024 / 32, 1024 / 32), tb>>>(l2w2, (__half*)sym(g_W_l2w2), 1024, 1024);
    k_cvtT_split_t<<<dim3(2048 / 32, 1024 / 32), tb>>>(g2w1, W_g2w1, 1024, 2048);
    k_cvtT_split_t<<<dim3(2048 / 32, 2048 / 32), tb>>>(g2w2, W_g2w2, 2048, 2048);
    k_cvt_wsw<<<(1024 * 1024 + 255) / 256, 256>>>(l2w2, W2sw, 1024, 1024, 1024);
    k_cvt_wsw<<<(512 * 1024 + 255) / 256, 256>>>(l2w1, Wsw_l2w1, 512, 1024, 1024);
    k_cvt_wsw<<<(1024 * 2048 + 255) / 256, 256>>>(g2w1, Wsw_g2w1, 1024, 2048, 2048);
    k_cvt_wsw<<<(2048 * 2048 + 255) / 256, 256>>>(g2w2, Wsw_g2w2, 2048, 2048, 2048);
    k_cvt_wsw<<<(128 * 256 + 255) / 256, 256>>>(g1w1, Wsw_g1w1, 128, 256, 256);
    k_cvt_wsw<<<(256 * 512 + 255) / 256, 256>>>(g1w2, Wsw_g1w2, 256, 512, 512);

    // conv1
    k_precomp1<<<(NN * 64 + 255) / 256, 256>>>(x, l1w1, l1b1);
    k_edge_gemm<64, 4><<<dim3(NE / 128, 1), 256, 128 * 130 * 4>>>(A1f, B1f, W_l1w2, l1b2, agg1);
    k_fin_hl<<<(NN * 128 + 255) / 256, 256>>>(agg1, agg1hl, 7, NN * 128);
    k_ngemm_tc<128, 0><<<dim3(40, 1), 512, EK_SMEM>>>(agg1hl, Wsw_g1w1, W_g1w1, g1b1,
                                                      T1hl, nullptr, nullptr, NN);
    k_ngemm_tc<256, 1><<<dim3(40, 2), 512, EK_SMEM>>>(T1hl, Wsw_g1w2, W_g1w2, g1b2,
                                                      nullptr, P1, nullptr, NN);
    k_stats_partial<<<dim3(4, MTILES), 128>>>(P1, 512);
    k_stats_final<<<4, 128>>>(512);
    k_norm_hl<<<(NN * 512 + 255) / 256, 256>>>(P1, gamma1, beta1, H1hl, 9, NN * 512);

    // conv2
    k_precompD2<<<(NN * 1024 + 255) / 256, 256>>>(x, l2w1);
    k_ngemm_tc<512, 2><<<dim3(40, 4), 512, EK_SMEM>>>(H1hl, Wsw_l2w1, W_l2w1, l2b1,
                                                      nullptr, C2f, D2f, NN);
    k_edge_act<<<NE, 256>>>(C2f, D2f);
    k_edge_tc<<<dim3(NE / 256, 4), 512, EK_SMEM>>>(l2b2, agg2);
    k_fin_hl<<<(NN * 1024 + 255) / 256, 256>>>(agg2, agg2hl, 10, NN * 1024);
    k_ngemm_tc<1024, 0><<<dim3(40, 8), 512, EK_SMEM>>>(agg2hl, Wsw_g2w1, W_g2w1, g2b1,
                                                       U2hl, nullptr, nullptr, NN);
    k_ngemm_tc<2048, 1><<<dim3(40, 8), 512, EK_SMEM>>>(U2hl, Wsw_g2w2, W_g2w2, g2b2,
                                                       nullptr, P2, nullptr, NN);
    k_stats_partial<<<dim3(16, MTILES), 128>>>(P2, 2048);
    k_stats_final<<<16, 128>>>(2048);
    k_norm_float<<<(NN * 2048 + 255) / 256, 256>>>(P2, gamma2, beta2, (float*)d_out, 2047,
                                                   NN * 2048);
}